// round 2
// baseline (speedup 1.0000x reference)
#include <cuda_runtime.h>
#include <math.h>
#include <stdint.h>

// Problem constants
#define BATCH   2
#define NSEQ    2048
#define DMODEL  1024
#define HEADS   16
#define DH      64
#define INNER   1024          // HEADS*DH
#define NROWS   (BATCH*NSEQ)  // 4096
#define SCALE   0.125f        // DH^-0.5
#define LN_EPS  1e-5f

// ---------------------------------------------------------------------------
// Scratch (no allocations allowed -> __device__ globals)
// ---------------------------------------------------------------------------
__device__ float g_xn [(size_t)NROWS * DMODEL];      // 16.8 MB
__device__ float g_qkv[(size_t)NROWS * 3 * INNER];   // 50.3 MB
__device__ float g_ctx[(size_t)NROWS * INNER];       // 16.8 MB

// ---------------------------------------------------------------------------
// Kernel 1: LayerNorm. One block per row, 256 threads, float4 per thread.
// ---------------------------------------------------------------------------
__global__ __launch_bounds__(256) void ln_kernel(
    const float* __restrict__ x, const float* __restrict__ gamma,
    const float* __restrict__ beta, float* __restrict__ xn)
{
    int row = blockIdx.x;
    int tid = threadIdx.x;
    const float4* xr = (const float4*)(x + (size_t)row * DMODEL);
    float4 v = xr[tid];

    float s  = v.x + v.y + v.z + v.w;
    float ss = v.x*v.x + v.y*v.y + v.z*v.z + v.w*v.w;

    #pragma unroll
    for (int off = 16; off; off >>= 1) {
        s  += __shfl_xor_sync(0xffffffffu, s,  off);
        ss += __shfl_xor_sync(0xffffffffu, ss, off);
    }
    __shared__ float sbuf[8], ssbuf[8];
    int warp = tid >> 5, lane = tid & 31;
    if (lane == 0) { sbuf[warp] = s; ssbuf[warp] = ss; }
    __syncthreads();
    s = 0.f; ss = 0.f;
    #pragma unroll
    for (int w = 0; w < 8; w++) { s += sbuf[w]; ss += ssbuf[w]; }

    float mu  = s * (1.0f / DMODEL);
    float var = ss * (1.0f / DMODEL) - mu * mu;
    float inv = rsqrtf(var + LN_EPS);

    float4 g  = ((const float4*)gamma)[tid];
    float4 be = ((const float4*)beta)[tid];
    float4 o;
    o.x = (v.x - mu) * inv * g.x + be.x;
    o.y = (v.y - mu) * inv * g.y + be.y;
    o.z = (v.z - mu) * inv * g.z + be.z;
    o.w = (v.w - mu) * inv * g.w + be.w;
    ((float4*)(xn + (size_t)row * DMODEL))[tid] = o;
}

// ---------------------------------------------------------------------------
// Kernel 2: fp32 SGEMM, C[M,N] = A[M,K] @ B[K,N], all row-major.
// 128x128 tile, BK=8, 256 threads, 8x8 micro-tile, double-buffered smem.
// M,N,K must be multiples of 128/128/8 (true for all uses here).
// ---------------------------------------------------------------------------
__global__ __launch_bounds__(256) void sgemm_kernel(
    const float* __restrict__ A, const float* __restrict__ B,
    float* __restrict__ C, int M, int N, int K)
{
    const int BM = 128, BN = 128, BK = 8;
    __shared__ float As[2][BK][BM];
    __shared__ float Bs[2][BK][BN];

    int tid = threadIdx.x;
    int bx = blockIdx.x, by = blockIdx.y;

    int arow = tid >> 1;            // 0..127
    int acol = (tid & 1) << 2;      // 0 / 4
    int brow = tid >> 5;            // 0..7
    int bcol = (tid & 31) << 2;     // 0..124

    const float* Ag = A + (size_t)(by * BM + arow) * K + acol;
    const float* Bg = B + (size_t)brow * N + (size_t)bx * BN + bcol;

    float4 a4 = *(const float4*)Ag;
    float4 b4 = *(const float4*)Bg;
    As[0][acol + 0][arow] = a4.x;
    As[0][acol + 1][arow] = a4.y;
    As[0][acol + 2][arow] = a4.z;
    As[0][acol + 3][arow] = a4.w;
    *(float4*)&Bs[0][brow][bcol] = b4;
    __syncthreads();

    int tx = (tid & 15) << 3;       // output col offset in tile
    int ty = (tid >> 4) << 3;       // output row offset in tile

    float acc[8][8];
    #pragma unroll
    for (int i = 0; i < 8; i++)
        #pragma unroll
        for (int j = 0; j < 8; j++) acc[i][j] = 0.f;

    int nk = K / BK;
    for (int kt = 0; kt < nk; kt++) {
        int cur = kt & 1;
        if (kt + 1 < nk) {
            a4 = *(const float4*)(Ag + (size_t)(kt + 1) * BK);
            b4 = *(const float4*)(Bg + (size_t)(kt + 1) * BK * N);
        }
        #pragma unroll
        for (int k = 0; k < BK; k++) {
            float4 a0 = *(const float4*)&As[cur][k][ty];
            float4 a1 = *(const float4*)&As[cur][k][ty + 4];
            float4 b0 = *(const float4*)&Bs[cur][k][tx];
            float4 b1 = *(const float4*)&Bs[cur][k][tx + 4];
            float av[8] = {a0.x, a0.y, a0.z, a0.w, a1.x, a1.y, a1.z, a1.w};
            float bv[8] = {b0.x, b0.y, b0.z, b0.w, b1.x, b1.y, b1.z, b1.w};
            #pragma unroll
            for (int i = 0; i < 8; i++)
                #pragma unroll
                for (int j = 0; j < 8; j++)
                    acc[i][j] += av[i] * bv[j];
        }
        if (kt + 1 < nk) {
            int nxt = cur ^ 1;
            As[nxt][acol + 0][arow] = a4.x;
            As[nxt][acol + 1][arow] = a4.y;
            As[nxt][acol + 2][arow] = a4.z;
            As[nxt][acol + 3][arow] = a4.w;
            *(float4*)&Bs[nxt][brow][bcol] = b4;
            __syncthreads();
        }
    }

    float* Cg = C + (size_t)(by * BM + ty) * N + (size_t)bx * BN + tx;
    #pragma unroll
    for (int i = 0; i < 8; i++) {
        float4 c0 = {acc[i][0], acc[i][1], acc[i][2], acc[i][3]};
        float4 c1 = {acc[i][4], acc[i][5], acc[i][6], acc[i][7]};
        *(float4*)(Cg + (size_t)i * N)     = c0;
        *(float4*)(Cg + (size_t)i * N + 4) = c1;
    }
}

// ---------------------------------------------------------------------------
// Kernel 3: flash-style masked attention (fp32).
// grid (NSEQ/64, HEADS, BATCH), 256 threads.
// dots = (Q K^T + m) * SCALE; online softmax; O = P V.
// qkv layout per row: [q(0..1023) | k(1024..2047) | v(2048..3071)],
// head h occupies cols h*64..h*64+63 inside each third.
// ---------------------------------------------------------------------------
#define ATTN_PAD 68
#define ATTN_SMEM (4 * 64 * ATTN_PAD * 4)   // Qt + Kt + Vs + Pt = 69632 B

__global__ __launch_bounds__(256) void attn_kernel(
    const float* __restrict__ qkv, const float* __restrict__ m,
    float* __restrict__ ctx)
{
    extern __shared__ float sm[];
    float (*Qt)[ATTN_PAD] = (float(*)[ATTN_PAD])(sm);                  // [d][qi]
    float (*Kt)[ATTN_PAD] = (float(*)[ATTN_PAD])(sm + 64 * ATTN_PAD);  // [d][kj]
    float (*Vs)[ATTN_PAD] = (float(*)[ATTN_PAD])(sm + 2 * 64 * ATTN_PAD); // [kj][d]
    float (*Pt)[ATTN_PAD] = (float(*)[ATTN_PAD])(sm + 3 * 64 * ATTN_PAD); // [j][qi]

    int tid = threadIdx.x;
    int qt = blockIdx.x, h = blockIdx.y, b = blockIdx.z;
    int q0 = qt * 64;
    size_t rowbase = (size_t)b * NSEQ;

    // Load Q tile transposed: Qt[d][qi]
    {
        int r  = tid >> 2;            // qi 0..63
        int c0 = (tid & 3) << 4;      // d offset 0/16/32/48
        const float* qg = qkv + (rowbase + q0 + r) * (size_t)(3 * INNER) + h * DH + c0;
        #pragma unroll
        for (int l = 0; l < 4; l++) {
            float4 v = *(const float4*)(qg + l * 4);
            int d0 = c0 + l * 4;
            Qt[d0 + 0][r] = v.x; Qt[d0 + 1][r] = v.y;
            Qt[d0 + 2][r] = v.z; Qt[d0 + 3][r] = v.w;
        }
    }

    int tx = tid & 15, ty = tid >> 4;
    int rr = ty * 4;   // local row base (qi)
    int cc = tx * 4;   // local col base (kj for S; d for O)

    float rmax[4], rsum[4], o[4][4];
    #pragma unroll
    for (int i = 0; i < 4; i++) {
        rmax[i] = -1e30f; rsum[i] = 0.f;
        #pragma unroll
        for (int j = 0; j < 4; j++) o[i][j] = 0.f;
    }

    for (int kt = 0; kt < NSEQ / 64; kt++) {
        int k0 = kt * 64;
        // Load K (transposed) and V (straight)
        {
            int r   = tid >> 2;
            int c0l = (tid & 3) << 4;
            const float* kg = qkv + (rowbase + k0 + r) * (size_t)(3 * INNER) + INNER   + h * DH + c0l;
            const float* vg = qkv + (rowbase + k0 + r) * (size_t)(3 * INNER) + 2*INNER + h * DH + c0l;
            #pragma unroll
            for (int l = 0; l < 4; l++) {
                float4 kv = *(const float4*)(kg + l * 4);
                int d0 = c0l + l * 4;
                Kt[d0 + 0][r] = kv.x; Kt[d0 + 1][r] = kv.y;
                Kt[d0 + 2][r] = kv.z; Kt[d0 + 3][r] = kv.w;
                float4 vv = *(const float4*)(vg + l * 4);
                *(float4*)&Vs[r][d0] = vv;
            }
        }
        __syncthreads();

        // S = Q K^T  (4x4 per thread)
        float s[4][4];
        #pragma unroll
        for (int i = 0; i < 4; i++)
            #pragma unroll
            for (int j = 0; j < 4; j++) s[i][j] = 0.f;

        #pragma unroll 8
        for (int k = 0; k < 64; k++) {
            float4 a  = *(const float4*)&Qt[k][rr];
            float4 bb = *(const float4*)&Kt[k][cc];
            float av[4] = {a.x, a.y, a.z, a.w};
            float bv[4] = {bb.x, bb.y, bb.z, bb.w};
            #pragma unroll
            for (int i = 0; i < 4; i++)
                #pragma unroll
                for (int j = 0; j < 4; j++)
                    s[i][j] += av[i] * bv[j];
        }

        // mask before scale (non-standard order per reference)
        const float* mg = m + ((size_t)b * NSEQ + q0 + rr) * NSEQ + k0 + cc;
        #pragma unroll
        for (int i = 0; i < 4; i++) {
            float4 mm = *(const float4*)(mg + (size_t)i * NSEQ);
            s[i][0] = (s[i][0] + mm.x) * SCALE;
            s[i][1] = (s[i][1] + mm.y) * SCALE;
            s[i][2] = (s[i][2] + mm.z) * SCALE;
            s[i][3] = (s[i][3] + mm.w) * SCALE;
        }

        // online softmax across the 16 threads sharing each row
        #pragma unroll
        for (int i = 0; i < 4; i++) {
            float tm = fmaxf(fmaxf(s[i][0], s[i][1]), fmaxf(s[i][2], s[i][3]));
            #pragma unroll
            for (int off = 8; off; off >>= 1)
                tm = fmaxf(tm, __shfl_xor_sync(0xffffffffu, tm, off));
            float nm   = fmaxf(rmax[i], tm);
            float corr = __expf(rmax[i] - nm);
            float ps = 0.f;
            #pragma unroll
            for (int j = 0; j < 4; j++) {
                float p = __expf(s[i][j] - nm);
                s[i][j] = p; ps += p;
            }
            #pragma unroll
            for (int off = 8; off; off >>= 1)
                ps += __shfl_xor_sync(0xffffffffu, ps, off);
            rsum[i] = rsum[i] * corr + ps;
            rmax[i] = nm;
            #pragma unroll
            for (int j = 0; j < 4; j++) o[i][j] *= corr;
        }

        // stage P transposed for the PV gemm
        #pragma unroll
        for (int j = 0; j < 4; j++)
            #pragma unroll
            for (int i = 0; i < 4; i++)
                Pt[cc + j][rr + i] = s[i][j];
        __syncthreads();

        // O += P V
        #pragma unroll 8
        for (int j = 0; j < 64; j++) {
            float4 p  = *(const float4*)&Pt[j][rr];
            float4 vv = *(const float4*)&Vs[j][cc];
            o[0][0] += p.x * vv.x; o[0][1] += p.x * vv.y; o[0][2] += p.x * vv.z; o[0][3] += p.x * vv.w;
            o[1][0] += p.y * vv.x; o[1][1] += p.y * vv.y; o[1][2] += p.y * vv.z; o[1][3] += p.y * vv.w;
            o[2][0] += p.z * vv.x; o[2][1] += p.z * vv.y; o[2][2] += p.z * vv.z; o[2][3] += p.z * vv.w;
            o[3][0] += p.w * vv.x; o[3][1] += p.w * vv.y; o[3][2] += p.w * vv.z; o[3][3] += p.w * vv.w;
        }
        __syncthreads();  // protect Kt/Vs/Pt before next tile's loads
    }

    // normalize and write ctx in [b, n, h*64 + d] layout
    #pragma unroll
    for (int i = 0; i < 4; i++) {
        float inv = 1.0f / rsum[i];
        float4 ov = {o[i][0] * inv, o[i][1] * inv, o[i][2] * inv, o[i][3] * inv};
        float* cg = ctx + (rowbase + q0 + rr + i) * (size_t)INNER + h * DH + cc;
        *(float4*)cg = ov;
    }
}

// ---------------------------------------------------------------------------
// launch
// ---------------------------------------------------------------------------
extern "C" void kernel_launch(void* const* d_in, const int* in_sizes, int n_in,
                              void* d_out, int out_size)
{
    const float* x     = (const float*)d_in[0];
    const float* m     = (const float*)d_in[1];
    const float* gamma = (const float*)d_in[2];
    const float* beta  = (const float*)d_in[3];
    const float* Wqkv  = (const float*)d_in[4];
    const float* Wout  = (const float*)d_in[5];
    float* out = (float*)d_out;

    float *xn, *qkvp, *ctx;
    cudaGetSymbolAddress((void**)&xn,   g_xn);
    cudaGetSymbolAddress((void**)&qkvp, g_qkv);
    cudaGetSymbolAddress((void**)&ctx,  g_ctx);

    cudaFuncSetAttribute(attn_kernel,
                         cudaFuncAttributeMaxDynamicSharedMemorySize, ATTN_SMEM);

    // 1. LayerNorm
    ln_kernel<<<NROWS, 256>>>(x, gamma, beta, xn);

    // 2. QKV projection: [4096,1024] @ [1024,3072]
    sgemm_kernel<<<dim3(3 * INNER / 128, NROWS / 128), 256>>>(
        xn, Wqkv, qkvp, NROWS, 3 * INNER, DMODEL);

    // 3. masked flash attention
    attn_kernel<<<dim3(NSEQ / 64, HEADS, BATCH), 256, ATTN_SMEM>>>(qkvp, m, ctx);

    // 4. output projection: [4096,1024] @ [1024,1024]
    sgemm_kernel<<<dim3(DMODEL / 128, NROWS / 128), 256>>>(
        ctx, Wout, out, NROWS, DMODEL, DMODEL);
}

// round 3
// speedup vs baseline: 1.0002x; 1.0002x over previous
#include <cuda_runtime.h>
#include <math.h>
#include <stdint.h>

// Problem constants
#define BATCH   2
#define NSEQ    2048
#define DMODEL  1024
#define HEADS   16
#define DH      64
#define INNER   1024          // HEADS*DH
#define NROWS   (BATCH*NSEQ)  // 4096
#define SCALE   0.125f        // DH^-0.5
#define LN_EPS  1e-5f

// ---------------------------------------------------------------------------
// Scratch (no allocations allowed -> __device__ globals)
// ---------------------------------------------------------------------------
__device__ float g_xn [(size_t)NROWS * DMODEL];      // 16.8 MB
__device__ float g_qkv[(size_t)NROWS * 3 * INNER];   // 50.3 MB
__device__ float g_ctx[(size_t)NROWS * INNER];       // 16.8 MB

// ---------------------------------------------------------------------------
// Kernel 1: LayerNorm. One block per row, 256 threads, float4 per thread.
// ---------------------------------------------------------------------------
__global__ __launch_bounds__(256) void ln_kernel(
    const float* __restrict__ x, const float* __restrict__ gamma,
    const float* __restrict__ beta, float* __restrict__ xn)
{
    int row = blockIdx.x;
    int tid = threadIdx.x;
    const float4* xr = (const float4*)(x + (size_t)row * DMODEL);
    float4 v = xr[tid];

    float s  = v.x + v.y + v.z + v.w;
    float ss = v.x*v.x + v.y*v.y + v.z*v.z + v.w*v.w;

    #pragma unroll
    for (int off = 16; off; off >>= 1) {
        s  += __shfl_xor_sync(0xffffffffu, s,  off);
        ss += __shfl_xor_sync(0xffffffffu, ss, off);
    }
    __shared__ float sbuf[8], ssbuf[8];
    int warp = tid >> 5, lane = tid & 31;
    if (lane == 0) { sbuf[warp] = s; ssbuf[warp] = ss; }
    __syncthreads();
    s = 0.f; ss = 0.f;
    #pragma unroll
    for (int w = 0; w < 8; w++) { s += sbuf[w]; ss += ssbuf[w]; }

    float mu  = s * (1.0f / DMODEL);
    float var = ss * (1.0f / DMODEL) - mu * mu;
    float inv = rsqrtf(var + LN_EPS);

    float4 g  = ((const float4*)gamma)[tid];
    float4 be = ((const float4*)beta)[tid];
    float4 o;
    o.x = (v.x - mu) * inv * g.x + be.x;
    o.y = (v.y - mu) * inv * g.y + be.y;
    o.z = (v.z - mu) * inv * g.z + be.z;
    o.w = (v.w - mu) * inv * g.w + be.w;
    ((float4*)(xn + (size_t)row * DMODEL))[tid] = o;
}

// ---------------------------------------------------------------------------
// Kernel 2: fp32 SGEMM, C[M,N] = A[M,K] @ B[K,N], all row-major.
// 128x128 tile, BK=8, 256 threads, 8x8 micro-tile, double-buffered smem.
// M,N,K must be multiples of 128/128/8 (true for all uses here).
// ---------------------------------------------------------------------------
__global__ __launch_bounds__(256) void sgemm_kernel(
    const float* __restrict__ A, const float* __restrict__ B,
    float* __restrict__ C, int M, int N, int K)
{
    const int BM = 128, BN = 128, BK = 8;
    __shared__ float As[2][BK][BM];
    __shared__ float Bs[2][BK][BN];

    int tid = threadIdx.x;
    int bx = blockIdx.x, by = blockIdx.y;

    int arow = tid >> 1;            // 0..127
    int acol = (tid & 1) << 2;      // 0 / 4
    int brow = tid >> 5;            // 0..7
    int bcol = (tid & 31) << 2;     // 0..124

    const float* Ag = A + (size_t)(by * BM + arow) * K + acol;
    const float* Bg = B + (size_t)brow * N + (size_t)bx * BN + bcol;

    float4 a4 = *(const float4*)Ag;
    float4 b4 = *(const float4*)Bg;
    As[0][acol + 0][arow] = a4.x;
    As[0][acol + 1][arow] = a4.y;
    As[0][acol + 2][arow] = a4.z;
    As[0][acol + 3][arow] = a4.w;
    *(float4*)&Bs[0][brow][bcol] = b4;
    __syncthreads();

    int tx = (tid & 15) << 3;       // output col offset in tile
    int ty = (tid >> 4) << 3;       // output row offset in tile

    float acc[8][8];
    #pragma unroll
    for (int i = 0; i < 8; i++)
        #pragma unroll
        for (int j = 0; j < 8; j++) acc[i][j] = 0.f;

    int nk = K / BK;
    for (int kt = 0; kt < nk; kt++) {
        int cur = kt & 1;
        if (kt + 1 < nk) {
            a4 = *(const float4*)(Ag + (size_t)(kt + 1) * BK);
            b4 = *(const float4*)(Bg + (size_t)(kt + 1) * BK * N);
        }
        #pragma unroll
        for (int k = 0; k < BK; k++) {
            float4 a0 = *(const float4*)&As[cur][k][ty];
            float4 a1 = *(const float4*)&As[cur][k][ty + 4];
            float4 b0 = *(const float4*)&Bs[cur][k][tx];
            float4 b1 = *(const float4*)&Bs[cur][k][tx + 4];
            float av[8] = {a0.x, a0.y, a0.z, a0.w, a1.x, a1.y, a1.z, a1.w};
            float bv[8] = {b0.x, b0.y, b0.z, b0.w, b1.x, b1.y, b1.z, b1.w};
            #pragma unroll
            for (int i = 0; i < 8; i++)
                #pragma unroll
                for (int j = 0; j < 8; j++)
                    acc[i][j] += av[i] * bv[j];
        }
        if (kt + 1 < nk) {
            int nxt = cur ^ 1;
            As[nxt][acol + 0][arow] = a4.x;
            As[nxt][acol + 1][arow] = a4.y;
            As[nxt][acol + 2][arow] = a4.z;
            As[nxt][acol + 3][arow] = a4.w;
            *(float4*)&Bs[nxt][brow][bcol] = b4;
            __syncthreads();
        }
    }

    float* Cg = C + (size_t)(by * BM + ty) * N + (size_t)bx * BN + tx;
    #pragma unroll
    for (int i = 0; i < 8; i++) {
        float4 c0 = {acc[i][0], acc[i][1], acc[i][2], acc[i][3]};
        float4 c1 = {acc[i][4], acc[i][5], acc[i][6], acc[i][7]};
        *(float4*)(Cg + (size_t)i * N)     = c0;
        *(float4*)(Cg + (size_t)i * N + 4) = c1;
    }
}

// ---------------------------------------------------------------------------
// Kernel 3: flash-style masked attention (fp32).
// grid (NSEQ/64, HEADS, BATCH), 256 threads.
// dots = (Q K^T + m) * SCALE; online softmax; O = P V.
// qkv layout per row: [q(0..1023) | k(1024..2047) | v(2048..3071)],
// head h occupies cols h*64..h*64+63 inside each third.
// ---------------------------------------------------------------------------
#define ATTN_PAD 68
#define ATTN_SMEM (4 * 64 * ATTN_PAD * 4)   // Qt + Kt + Vs + Pt = 69632 B

__global__ __launch_bounds__(256) void attn_kernel(
    const float* __restrict__ qkv, const float* __restrict__ m,
    float* __restrict__ ctx)
{
    extern __shared__ float sm[];
    float (*Qt)[ATTN_PAD] = (float(*)[ATTN_PAD])(sm);                  // [d][qi]
    float (*Kt)[ATTN_PAD] = (float(*)[ATTN_PAD])(sm + 64 * ATTN_PAD);  // [d][kj]
    float (*Vs)[ATTN_PAD] = (float(*)[ATTN_PAD])(sm + 2 * 64 * ATTN_PAD); // [kj][d]
    float (*Pt)[ATTN_PAD] = (float(*)[ATTN_PAD])(sm + 3 * 64 * ATTN_PAD); // [j][qi]

    int tid = threadIdx.x;
    int qt = blockIdx.x, h = blockIdx.y, b = blockIdx.z;
    int q0 = qt * 64;
    size_t rowbase = (size_t)b * NSEQ;

    // Load Q tile transposed: Qt[d][qi]
    {
        int r  = tid >> 2;            // qi 0..63
        int c0 = (tid & 3) << 4;      // d offset 0/16/32/48
        const float* qg = qkv + (rowbase + q0 + r) * (size_t)(3 * INNER) + h * DH + c0;
        #pragma unroll
        for (int l = 0; l < 4; l++) {
            float4 v = *(const float4*)(qg + l * 4);
            int d0 = c0 + l * 4;
            Qt[d0 + 0][r] = v.x; Qt[d0 + 1][r] = v.y;
            Qt[d0 + 2][r] = v.z; Qt[d0 + 3][r] = v.w;
        }
    }

    int tx = tid & 15, ty = tid >> 4;
    int rr = ty * 4;   // local row base (qi)
    int cc = tx * 4;   // local col base (kj for S; d for O)

    float rmax[4], rsum[4], o[4][4];
    #pragma unroll
    for (int i = 0; i < 4; i++) {
        rmax[i] = -1e30f; rsum[i] = 0.f;
        #pragma unroll
        for (int j = 0; j < 4; j++) o[i][j] = 0.f;
    }

    for (int kt = 0; kt < NSEQ / 64; kt++) {
        int k0 = kt * 64;
        // Load K (transposed) and V (straight)
        {
            int r   = tid >> 2;
            int c0l = (tid & 3) << 4;
            const float* kg = qkv + (rowbase + k0 + r) * (size_t)(3 * INNER) + INNER   + h * DH + c0l;
            const float* vg = qkv + (rowbase + k0 + r) * (size_t)(3 * INNER) + 2*INNER + h * DH + c0l;
            #pragma unroll
            for (int l = 0; l < 4; l++) {
                float4 kv = *(const float4*)(kg + l * 4);
                int d0 = c0l + l * 4;
                Kt[d0 + 0][r] = kv.x; Kt[d0 + 1][r] = kv.y;
                Kt[d0 + 2][r] = kv.z; Kt[d0 + 3][r] = kv.w;
                float4 vv = *(const float4*)(vg + l * 4);
                *(float4*)&Vs[r][d0] = vv;
            }
        }
        __syncthreads();

        // S = Q K^T  (4x4 per thread)
        float s[4][4];
        #pragma unroll
        for (int i = 0; i < 4; i++)
            #pragma unroll
            for (int j = 0; j < 4; j++) s[i][j] = 0.f;

        #pragma unroll 8
        for (int k = 0; k < 64; k++) {
            float4 a  = *(const float4*)&Qt[k][rr];
            float4 bb = *(const float4*)&Kt[k][cc];
            float av[4] = {a.x, a.y, a.z, a.w};
            float bv[4] = {bb.x, bb.y, bb.z, bb.w};
            #pragma unroll
            for (int i = 0; i < 4; i++)
                #pragma unroll
                for (int j = 0; j < 4; j++)
                    s[i][j] += av[i] * bv[j];
        }

        // mask before scale (non-standard order per reference)
        const float* mg = m + ((size_t)b * NSEQ + q0 + rr) * NSEQ + k0 + cc;
        #pragma unroll
        for (int i = 0; i < 4; i++) {
            float4 mm = *(const float4*)(mg + (size_t)i * NSEQ);
            s[i][0] = (s[i][0] + mm.x) * SCALE;
            s[i][1] = (s[i][1] + mm.y) * SCALE;
            s[i][2] = (s[i][2] + mm.z) * SCALE;
            s[i][3] = (s[i][3] + mm.w) * SCALE;
        }

        // online softmax across the 16 threads sharing each row
        #pragma unroll
        for (int i = 0; i < 4; i++) {
            float tm = fmaxf(fmaxf(s[i][0], s[i][1]), fmaxf(s[i][2], s[i][3]));
            #pragma unroll
            for (int off = 8; off; off >>= 1)
                tm = fmaxf(tm, __shfl_xor_sync(0xffffffffu, tm, off));
            float nm   = fmaxf(rmax[i], tm);
            float corr = __expf(rmax[i] - nm);
            float ps = 0.f;
            #pragma unroll
            for (int j = 0; j < 4; j++) {
                float p = __expf(s[i][j] - nm);
                s[i][j] = p; ps += p;
            }
            #pragma unroll
            for (int off = 8; off; off >>= 1)
                ps += __shfl_xor_sync(0xffffffffu, ps, off);
            rsum[i] = rsum[i] * corr + ps;
            rmax[i] = nm;
            #pragma unroll
            for (int j = 0; j < 4; j++) o[i][j] *= corr;
        }

        // stage P transposed for the PV gemm
        #pragma unroll
        for (int j = 0; j < 4; j++)
            #pragma unroll
            for (int i = 0; i < 4; i++)
                Pt[cc + j][rr + i] = s[i][j];
        __syncthreads();

        // O += P V
        #pragma unroll 8
        for (int j = 0; j < 64; j++) {
            float4 p  = *(const float4*)&Pt[j][rr];
            float4 vv = *(const float4*)&Vs[j][cc];
            o[0][0] += p.x * vv.x; o[0][1] += p.x * vv.y; o[0][2] += p.x * vv.z; o[0][3] += p.x * vv.w;
            o[1][0] += p.y * vv.x; o[1][1] += p.y * vv.y; o[1][2] += p.y * vv.z; o[1][3] += p.y * vv.w;
            o[2][0] += p.z * vv.x; o[2][1] += p.z * vv.y; o[2][2] += p.z * vv.z; o[2][3] += p.z * vv.w;
            o[3][0] += p.w * vv.x; o[3][1] += p.w * vv.y; o[3][2] += p.w * vv.z; o[3][3] += p.w * vv.w;
        }
        __syncthreads();  // protect Kt/Vs/Pt before next tile's loads
    }

    // normalize and write ctx in [b, n, h*64 + d] layout
    #pragma unroll
    for (int i = 0; i < 4; i++) {
        float inv = 1.0f / rsum[i];
        float4 ov = {o[i][0] * inv, o[i][1] * inv, o[i][2] * inv, o[i][3] * inv};
        float* cg = ctx + (rowbase + q0 + rr + i) * (size_t)INNER + h * DH + cc;
        *(float4*)cg = ov;
    }
}

// ---------------------------------------------------------------------------
// launch
// ---------------------------------------------------------------------------
extern "C" void kernel_launch(void* const* d_in, const int* in_sizes, int n_in,
                              void* d_out, int out_size)
{
    const float* x     = (const float*)d_in[0];
    const float* m     = (const float*)d_in[1];
    const float* gamma = (const float*)d_in[2];
    const float* beta  = (const float*)d_in[3];
    const float* Wqkv  = (const float*)d_in[4];
    const float* Wout  = (const float*)d_in[5];
    float* out = (float*)d_out;

    float *xn, *qkvp, *ctx;
    cudaGetSymbolAddress((void**)&xn,   g_xn);
    cudaGetSymbolAddress((void**)&qkvp, g_qkv);
    cudaGetSymbolAddress((void**)&ctx,  g_ctx);

    cudaFuncSetAttribute(attn_kernel,
                         cudaFuncAttributeMaxDynamicSharedMemorySize, ATTN_SMEM);

    // 1. LayerNorm
    ln_kernel<<<NROWS, 256>>>(x, gamma, beta, xn);

    // 2. QKV projection: [4096,1024] @ [1024,3072]
    sgemm_kernel<<<dim3(3 * INNER / 128, NROWS / 128), 256>>>(
        xn, Wqkv, qkvp, NROWS, 3 * INNER, DMODEL);

    // 3. masked flash attention
    attn_kernel<<<dim3(NSEQ / 64, HEADS, BATCH), 256, ATTN_SMEM>>>(qkvp, m, ctx);

    // 4. output projection: [4096,1024] @ [1024,1024]
    sgemm_kernel<<<dim3(DMODEL / 128, NROWS / 128), 256>>>(
        ctx, Wout, out, NROWS, DMODEL, DMODEL);
}

// round 6
// speedup vs baseline: 1.3276x; 1.3273x over previous
#include <cuda_runtime.h>
#include <cuda_bf16.h>
#include <math.h>
#include <stdint.h>

// ---------------------------------------------------------------------------
// Problem constants
// ---------------------------------------------------------------------------
#define BATCH   2
#define NSEQ    2048
#define DMODEL  1024
#define HEADS   16
#define DH      64
#define INNER   1024
#define NROWS   (BATCH*NSEQ)   // 4096
#define SCALE   0.125f
#define LN_EPS  1e-5f

// ---------------------------------------------------------------------------
// Scratch (__device__ globals; no allocs allowed)
// ---------------------------------------------------------------------------
__device__ float         g_qkv [(size_t)NROWS * 3 * INNER];   // fp32 QKV
__device__ __nv_bfloat16 g_xn_h[(size_t)NROWS * DMODEL];
__device__ __nv_bfloat16 g_xn_l[(size_t)NROWS * DMODEL];
__device__ __nv_bfloat16 g_wq_h[(size_t)3*INNER * DMODEL];    // Wqkv^T [3072][1024]
__device__ __nv_bfloat16 g_wq_l[(size_t)3*INNER * DMODEL];
__device__ __nv_bfloat16 g_wo_h[(size_t)DMODEL * INNER];      // Wout^T [1024][1024]
__device__ __nv_bfloat16 g_wo_l[(size_t)DMODEL * INNER];
__device__ __nv_bfloat16 g_ctx_h[(size_t)NROWS * INNER];
__device__ __nv_bfloat16 g_ctx_l[(size_t)NROWS * INNER];

// ---------------------------------------------------------------------------
// Helpers
// ---------------------------------------------------------------------------
__device__ __forceinline__ void split1(float v, __nv_bfloat16& h, __nv_bfloat16& l) {
    h = __float2bfloat16(v);
    l = __float2bfloat16(v - __bfloat162float(h));
}

__device__ __forceinline__ void ldsm4(uint32_t* r, uint32_t addr) {
    asm volatile("ldmatrix.sync.aligned.m8n8.x4.shared.b16 {%0,%1,%2,%3}, [%4];"
                 : "=r"(r[0]), "=r"(r[1]), "=r"(r[2]), "=r"(r[3]) : "r"(addr));
}

__device__ __forceinline__ void mma16816(float* d, const uint32_t* a,
                                         const uint32_t* b) {
    asm volatile(
        "mma.sync.aligned.m16n8k16.row.col.f32.bf16.bf16.f32 "
        "{%0,%1,%2,%3}, {%4,%5,%6,%7}, {%8,%9}, {%0,%1,%2,%3};"
        : "+f"(d[0]), "+f"(d[1]), "+f"(d[2]), "+f"(d[3])
        : "r"(a[0]), "r"(a[1]), "r"(a[2]), "r"(a[3]), "r"(b[0]), "r"(b[1]));
}

__device__ __forceinline__ void cp16(uint32_t dst, const void* src) {
    asm volatile("cp.async.cg.shared.global [%0], [%1], 16;"
                 :: "r"(dst), "l"(__cvta_generic_to_global(src)));
}

// ---------------------------------------------------------------------------
// Kernel 1: LayerNorm fused with bf16 hi/lo split output
// ---------------------------------------------------------------------------
__global__ __launch_bounds__(256) void ln_kernel(
    const float* __restrict__ x, const float* __restrict__ gamma,
    const float* __restrict__ beta,
    __nv_bfloat16* __restrict__ xh, __nv_bfloat16* __restrict__ xl)
{
    int row = blockIdx.x;
    int tid = threadIdx.x;
    const float4* xr = (const float4*)(x + (size_t)row * DMODEL);
    float4 v = xr[tid];

    float s  = v.x + v.y + v.z + v.w;
    float ss = v.x*v.x + v.y*v.y + v.z*v.z + v.w*v.w;
    #pragma unroll
    for (int off = 16; off; off >>= 1) {
        s  += __shfl_xor_sync(0xffffffffu, s,  off);
        ss += __shfl_xor_sync(0xffffffffu, ss, off);
    }
    __shared__ float sbuf[8], ssbuf[8];
    int warp = tid >> 5, lane = tid & 31;
    if (lane == 0) { sbuf[warp] = s; ssbuf[warp] = ss; }
    __syncthreads();
    s = 0.f; ss = 0.f;
    #pragma unroll
    for (int w = 0; w < 8; w++) { s += sbuf[w]; ss += ssbuf[w]; }

    float mu  = s * (1.0f / DMODEL);
    float var = ss * (1.0f / DMODEL) - mu * mu;
    float inv = rsqrtf(var + LN_EPS);

    float4 g  = ((const float4*)gamma)[tid];
    float4 be = ((const float4*)beta)[tid];
    float o0 = (v.x - mu) * inv * g.x + be.x;
    float o1 = (v.y - mu) * inv * g.y + be.y;
    float o2 = (v.z - mu) * inv * g.z + be.z;
    float o3 = (v.w - mu) * inv * g.w + be.w;

    __nv_bfloat16 h0,h1,h2,h3,l0,l1,l2,l3;
    split1(o0,h0,l0); split1(o1,h1,l1); split1(o2,h2,l2); split1(o3,h3,l3);
    size_t off = (size_t)row * DMODEL + tid * 4;
    ushort4 hv = { __bfloat16_as_ushort(h0), __bfloat16_as_ushort(h1),
                   __bfloat16_as_ushort(h2), __bfloat16_as_ushort(h3) };
    ushort4 lv = { __bfloat16_as_ushort(l0), __bfloat16_as_ushort(l1),
                   __bfloat16_as_ushort(l2), __bfloat16_as_ushort(l3) };
    *(ushort4*)(xh + off) = hv;
    *(ushort4*)(xl + off) = lv;
}

// ---------------------------------------------------------------------------
// Kernel 2: transpose + bf16 split for weights: W[K,N] fp32 -> T[N,K] bf16 hi/lo
// ---------------------------------------------------------------------------
__global__ __launch_bounds__(256) void splitT_kernel(
    const float* __restrict__ W,
    __nv_bfloat16* __restrict__ Th, __nv_bfloat16* __restrict__ Tl,
    int K, int N)
{
    __shared__ float t[32][33];
    int n0 = blockIdx.x * 32, k0 = blockIdx.y * 32;
    int tx = threadIdx.x, ty = threadIdx.y;
    #pragma unroll
    for (int j = 0; j < 4; j++) {
        int r = ty + j * 8;
        t[r][tx] = W[(size_t)(k0 + r) * N + n0 + tx];
    }
    __syncthreads();
    #pragma unroll
    for (int j = 0; j < 4; j++) {
        int r = ty + j * 8;           // local n
        float v = t[tx][r];
        __nv_bfloat16 h, l;
        split1(v, h, l);
        size_t o = (size_t)(n0 + r) * K + k0 + tx;
        Th[o] = h; Tl[o] = l;
    }
}

// ---------------------------------------------------------------------------
// Kernel 3: bf16x3-split GEMM on mma.sync (HMMA).
// C[M,N](fp32) = A[M,1024] @ B[1024,N], A row-major hi/lo bf16,
// B supplied transposed ([N][K] row-major) hi/lo bf16.
// Block 128x128, BK=32, 8 warps (2x4), warp tile 64x32, cp.async 2-stage.
// ---------------------------------------------------------------------------
#define GK      1024
#define GBK     32
#define GSTRIDE 40                         // smem row stride in bf16 elems
#define GBUF    (128 * GSTRIDE)            // elems per buffer
#define GSMEM   (8 * GBUF * 2)             // bytes: {Ah,Al,Bh,Bl} x 2 stages

__global__ __launch_bounds__(256) void mma_gemm(
    const __nv_bfloat16* __restrict__ Ah, const __nv_bfloat16* __restrict__ Al,
    const __nv_bfloat16* __restrict__ Bh, const __nv_bfloat16* __restrict__ Bl,
    float* __restrict__ C, int N)
{
    extern __shared__ __nv_bfloat16 smg[];
    __nv_bfloat16* sAh = smg;
    __nv_bfloat16* sAl = smg + 2 * GBUF;
    __nv_bfloat16* sBh = smg + 4 * GBUF;
    __nv_bfloat16* sBl = smg + 6 * GBUF;

    const int tid  = threadIdx.x;
    const int lane = tid & 31, wid = tid >> 5;
    const int wm = wid >> 2, wn = wid & 3;            // 2 x 4 warp grid
    const int m0 = blockIdx.y * 128, n0 = blockIdx.x * 128;

    const uint32_t uAh = (uint32_t)__cvta_generic_to_shared(sAh);
    const uint32_t uAl = (uint32_t)__cvta_generic_to_shared(sAl);
    const uint32_t uBh = (uint32_t)__cvta_generic_to_shared(sBh);
    const uint32_t uBl = (uint32_t)__cvta_generic_to_shared(sBl);

    // copy indices: 2 x 16B per thread per buffer
    const int cr0 = (tid)        >> 2, cs0 = (tid)        & 3;
    const int cr1 = (tid + 256)  >> 2, cs1 = (tid + 256)  & 3;

    float acc[4][4][4];
    #pragma unroll
    for (int f = 0; f < 4; f++)
        #pragma unroll
        for (int j = 0; j < 4; j++)
            #pragma unroll
            for (int e = 0; e < 4; e++) acc[f][j][e] = 0.f;

    // ldmatrix lane offsets (bytes, within a buffer)
    const uint32_t aoff = ((uint32_t)((wm*64 + (lane & 15)) * GSTRIDE
                          + (lane >> 4) * 8)) * 2;
    const uint32_t boff = ((uint32_t)((wn*32 + (lane & 7) + ((lane >> 4) << 3)) * GSTRIDE
                          + ((lane >> 3) & 1) * 8)) * 2;

#define STAGE_COPY(stage, kc)                                                   \
    do {                                                                        \
        uint32_t so = (uint32_t)(stage) * GBUF * 2;                             \
        uint32_t d0 = (uint32_t)(cr0 * GSTRIDE + cs0 * 8) * 2 + so;             \
        uint32_t d1 = (uint32_t)(cr1 * GSTRIDE + cs1 * 8) * 2 + so;             \
        size_t ga0 = (size_t)(m0 + cr0) * GK + (kc) + cs0 * 8;                  \
        size_t ga1 = (size_t)(m0 + cr1) * GK + (kc) + cs1 * 8;                  \
        size_t gb0 = (size_t)(n0 + cr0) * GK + (kc) + cs0 * 8;                  \
        size_t gb1 = (size_t)(n0 + cr1) * GK + (kc) + cs1 * 8;                  \
        cp16(uAh + d0, Ah + ga0); cp16(uAh + d1, Ah + ga1);                     \
        cp16(uAl + d0, Al + ga0); cp16(uAl + d1, Al + ga1);                     \
        cp16(uBh + d0, Bh + gb0); cp16(uBh + d1, Bh + gb1);                     \
        cp16(uBl + d0, Bl + gb0); cp16(uBl + d1, Bl + gb1);                     \
    } while (0)

    STAGE_COPY(0, 0);
    asm volatile("cp.async.commit_group;" ::: "memory");

    const int nk = GK / GBK;    // 32
    for (int kt = 0; kt < nk; kt++) {
        const int stage = kt & 1;
        if (kt + 1 < nk) {
            STAGE_COPY(stage ^ 1, (kt + 1) * GBK);
            asm volatile("cp.async.commit_group;" ::: "memory");
            asm volatile("cp.async.wait_group 1;" ::: "memory");
        } else {
            asm volatile("cp.async.wait_group 0;" ::: "memory");
        }
        __syncthreads();

        const uint32_t so = (uint32_t)stage * GBUF * 2;
        #pragma unroll
        for (int ks = 0; ks < 2; ks++) {
            uint32_t ah[4][4], al[4][4], bh[2][4], bl[2][4];
            #pragma unroll
            for (int f = 0; f < 4; f++) {
                uint32_t o = so + aoff + (uint32_t)(f * 16 * GSTRIDE + ks * 16) * 2;
                ldsm4(ah[f], uAh + o);
                ldsm4(al[f], uAl + o);
            }
            #pragma unroll
            for (int p = 0; p < 2; p++) {
                uint32_t o = so + boff + (uint32_t)(p * 16 * GSTRIDE + ks * 16) * 2;
                ldsm4(bh[p], uBh + o);
                ldsm4(bl[p], uBl + o);
            }
            #pragma unroll
            for (int f = 0; f < 4; f++) {
                #pragma unroll
                for (int j = 0; j < 4; j++) {
                    const int p = j >> 1, sub = (j & 1) * 2;
                    uint32_t bhp[2] = { bh[p][sub], bh[p][sub + 1] };
                    uint32_t blp[2] = { bl[p][sub], bl[p][sub + 1] };
                    mma16816(acc[f][j], ah[f], bhp);   // Ah*Bh
                    mma16816(acc[f][j], ah[f], blp);   // Ah*Bl
                    mma16816(acc[f][j], al[f], bhp);   // Al*Bh
                }
            }
        }
        __syncthreads();
    }

    // epilogue: D fragment (m16n8): d0,d1 @ (row=t/4, col=2*(t%4)), d2,d3 @ row+8
    const int erow = m0 + wm * 64 + (lane >> 2);
    const int ecol = n0 + wn * 32 + (lane & 3) * 2;
    #pragma unroll
    for (int f = 0; f < 4; f++) {
        #pragma unroll
        for (int j = 0; j < 4; j++) {
            float* d0 = C + (size_t)(erow + f * 16)     * N + ecol + j * 8;
            float* d1 = C + (size_t)(erow + f * 16 + 8) * N + ecol + j * 8;
            *(float2*)d0 = make_float2(acc[f][j][0], acc[f][j][1]);
            *(float2*)d1 = make_float2(acc[f][j][2], acc[f][j][3]);
        }
    }
#undef STAGE_COPY
}

// ---------------------------------------------------------------------------
// Kernel 4: flash-style masked attention (fp32), writes ctx as bf16 hi/lo.
// ---------------------------------------------------------------------------
#define ATTN_PAD 68
#define ATTN_SMEM (4 * 64 * ATTN_PAD * 4)

__global__ __launch_bounds__(256) void attn_kernel(
    const float* __restrict__ qkv, const float* __restrict__ m,
    __nv_bfloat16* __restrict__ ctxh, __nv_bfloat16* __restrict__ ctxl)
{
    extern __shared__ float sm[];
    float (*Qt)[ATTN_PAD] = (float(*)[ATTN_PAD])(sm);
    float (*Kt)[ATTN_PAD] = (float(*)[ATTN_PAD])(sm + 64 * ATTN_PAD);
    float (*Vs)[ATTN_PAD] = (float(*)[ATTN_PAD])(sm + 2 * 64 * ATTN_PAD);
    float (*Pt)[ATTN_PAD] = (float(*)[ATTN_PAD])(sm + 3 * 64 * ATTN_PAD);

    int tid = threadIdx.x;
    int qt = blockIdx.x, h = blockIdx.y, b = blockIdx.z;
    int q0 = qt * 64;
    size_t rowbase = (size_t)b * NSEQ;

    {
        int r  = tid >> 2;
        int c0 = (tid & 3) << 4;
        const float* qg = qkv + (rowbase + q0 + r) * (size_t)(3 * INNER) + h * DH + c0;
        #pragma unroll
        for (int l = 0; l < 4; l++) {
            float4 v = *(const float4*)(qg + l * 4);
            int d0 = c0 + l * 4;
            Qt[d0 + 0][r] = v.x; Qt[d0 + 1][r] = v.y;
            Qt[d0 + 2][r] = v.z; Qt[d0 + 3][r] = v.w;
        }
    }

    int tx = tid & 15, ty = tid >> 4;
    int rr = ty * 4, cc = tx * 4;

    float rmax[4], rsum[4], o[4][4];
    #pragma unroll
    for (int i = 0; i < 4; i++) {
        rmax[i] = -1e30f; rsum[i] = 0.f;
        #pragma unroll
        for (int j = 0; j < 4; j++) o[i][j] = 0.f;
    }

    for (int kt = 0; kt < NSEQ / 64; kt++) {
        int k0 = kt * 64;
        {
            int r   = tid >> 2;
            int c0l = (tid & 3) << 4;
            const float* kg = qkv + (rowbase + k0 + r) * (size_t)(3 * INNER) + INNER   + h * DH + c0l;
            const float* vg = qkv + (rowbase + k0 + r) * (size_t)(3 * INNER) + 2*INNER + h * DH + c0l;
            #pragma unroll
            for (int l = 0; l < 4; l++) {
                float4 kv = *(const float4*)(kg + l * 4);
                int d0 = c0l + l * 4;
                Kt[d0 + 0][r] = kv.x; Kt[d0 + 1][r] = kv.y;
                Kt[d0 + 2][r] = kv.z; Kt[d0 + 3][r] = kv.w;
                float4 vv = *(const float4*)(vg + l * 4);
                *(float4*)&Vs[r][d0] = vv;
            }
        }
        __syncthreads();

        float s[4][4];
        #pragma unroll
        for (int i = 0; i < 4; i++)
            #pragma unroll
            for (int j = 0; j < 4; j++) s[i][j] = 0.f;

        #pragma unroll 8
        for (int k = 0; k < 64; k++) {
            float4 a  = *(const float4*)&Qt[k][rr];
            float4 bb = *(const float4*)&Kt[k][cc];
            float av[4] = {a.x, a.y, a.z, a.w};
            float bv[4] = {bb.x, bb.y, bb.z, bb.w};
            #pragma unroll
            for (int i = 0; i < 4; i++)
                #pragma unroll
                for (int j = 0; j < 4; j++)
                    s[i][j] += av[i] * bv[j];
        }

        const float* mg = m + ((size_t)b * NSEQ + q0 + rr) * NSEQ + k0 + cc;
        #pragma unroll
        for (int i = 0; i < 4; i++) {
            float4 mm = *(const float4*)(mg + (size_t)i * NSEQ);
            s[i][0] = (s[i][0] + mm.x) * SCALE;
            s[i][1] = (s[i][1] + mm.y) * SCALE;
            s[i][2] = (s[i][2] + mm.z) * SCALE;
            s[i][3] = (s[i][3] + mm.w) * SCALE;
        }

        #pragma unroll
        for (int i = 0; i < 4; i++) {
            float tm = fmaxf(fmaxf(s[i][0], s[i][1]), fmaxf(s[i][2], s[i][3]));
            #pragma unroll
            for (int off = 8; off; off >>= 1)
                tm = fmaxf(tm, __shfl_xor_sync(0xffffffffu, tm, off));
            float nm   = fmaxf(rmax[i], tm);
            float corr = __expf(rmax[i] - nm);
            float ps = 0.f;
            #pragma unroll
            for (int j = 0; j < 4; j++) {
                float p = __expf(s[i][j] - nm);
                s[i][j] = p; ps += p;
            }
            #pragma unroll
            for (int off = 8; off; off >>= 1)
                ps += __shfl_xor_sync(0xffffffffu, ps, off);
            rsum[i] = rsum[i] * corr + ps;
            rmax[i] = nm;
            #pragma unroll
            for (int j = 0; j < 4; j++) o[i][j] *= corr;
        }

        #pragma unroll
        for (int j = 0; j < 4; j++)
            #pragma unroll
            for (int i = 0; i < 4; i++)
                Pt[cc + j][rr + i] = s[i][j];
        __syncthreads();

        #pragma unroll 8
        for (int j = 0; j < 64; j++) {
            float4 p  = *(const float4*)&Pt[j][rr];
            float4 vv = *(const float4*)&Vs[j][cc];
            o[0][0] += p.x * vv.x; o[0][1] += p.x * vv.y; o[0][2] += p.x * vv.z; o[0][3] += p.x * vv.w;
            o[1][0] += p.y * vv.x; o[1][1] += p.y * vv.y; o[1][2] += p.y * vv.z; o[1][3] += p.y * vv.w;
            o[2][0] += p.z * vv.x; o[2][1] += p.z * vv.y; o[2][2] += p.z * vv.z; o[2][3] += p.z * vv.w;
            o[3][0] += p.w * vv.x; o[3][1] += p.w * vv.y; o[3][2] += p.w * vv.z; o[3][3] += p.w * vv.w;
        }
        __syncthreads();
    }

    #pragma unroll
    for (int i = 0; i < 4; i++) {
        float inv = 1.0f / rsum[i];
        float v0 = o[i][0]*inv, v1 = o[i][1]*inv, v2 = o[i][2]*inv, v3 = o[i][3]*inv;
        __nv_bfloat16 h0,h1,h2,h3,l0,l1,l2,l3;
        split1(v0,h0,l0); split1(v1,h1,l1); split1(v2,h2,l2); split1(v3,h3,l3);
        size_t off = (rowbase + q0 + rr + i) * (size_t)INNER + h * DH + cc;
        ushort4 hv = { __bfloat16_as_ushort(h0), __bfloat16_as_ushort(h1),
                       __bfloat16_as_ushort(h2), __bfloat16_as_ushort(h3) };
        ushort4 lv = { __bfloat16_as_ushort(l0), __bfloat16_as_ushort(l1),
                       __bfloat16_as_ushort(l2), __bfloat16_as_ushort(l3) };
        *(ushort4*)(ctxh + off) = hv;
        *(ushort4*)(ctxl + off) = lv;
    }
}

// ---------------------------------------------------------------------------
// launch
// ---------------------------------------------------------------------------
extern "C" void kernel_launch(void* const* d_in, const int* in_sizes, int n_in,
                              void* d_out, int out_size)
{
    const float* x     = (const float*)d_in[0];
    const float* m     = (const float*)d_in[1];
    const float* gamma = (const float*)d_in[2];
    const float* beta  = (const float*)d_in[3];
    const float* Wqkv  = (const float*)d_in[4];
    const float* Wout  = (const float*)d_in[5];
    float* out = (float*)d_out;

    float* qkvp;
    __nv_bfloat16 *xnh, *xnl, *wqh, *wql, *woh, *wol, *ctxh, *ctxl;
    cudaGetSymbolAddress((void**)&qkvp, g_qkv);
    cudaGetSymbolAddress((void**)&xnh,  g_xn_h);
    cudaGetSymbolAddress((void**)&xnl,  g_xn_l);
    cudaGetSymbolAddress((void**)&wqh,  g_wq_h);
    cudaGetSymbolAddress((void**)&wql,  g_wq_l);
    cudaGetSymbolAddress((void**)&woh,  g_wo_h);
    cudaGetSymbolAddress((void**)&wol,  g_wo_l);
    cudaGetSymbolAddress((void**)&ctxh, g_ctx_h);
    cudaGetSymbolAddress((void**)&ctxl, g_ctx_l);

    cudaFuncSetAttribute(mma_gemm,
                         cudaFuncAttributeMaxDynamicSharedMemorySize, GSMEM);
    cudaFuncSetAttribute(attn_kernel,
                         cudaFuncAttributeMaxDynamicSharedMemorySize, ATTN_SMEM);

    // 1. LayerNorm (+ bf16 split)
    ln_kernel<<<NROWS, 256>>>(x, gamma, beta, xnh, xnl);

    // 2. weight transpose + split
    splitT_kernel<<<dim3(3*INNER/32, DMODEL/32), dim3(32,8)>>>(Wqkv, wqh, wql, DMODEL, 3*INNER);
    splitT_kernel<<<dim3(DMODEL/32,  INNER/32),  dim3(32,8)>>>(Wout, woh, wol, INNER, DMODEL);

    // 3. QKV projection: [4096,1024] x [1024,3072] via mma.sync bf16x3
    mma_gemm<<<dim3(3*INNER/128, NROWS/128), 256, GSMEM>>>(
        xnh, xnl, wqh, wql, qkvp, 3*INNER);

    // 4. masked flash attention (fp32, emits ctx bf16 hi/lo)
    attn_kernel<<<dim3(NSEQ/64, HEADS, BATCH), 256, ATTN_SMEM>>>(qkvp, m, ctxh, ctxl);

    // 5. output projection: [4096,1024] x [1024,1024] via mma.sync bf16x3
    mma_gemm<<<dim3(DMODEL/128, NROWS/128), 256, GSMEM>>>(
        ctxh, ctxl, woh, wol, out, DMODEL);
}

// round 7
// speedup vs baseline: 2.3810x; 1.7934x over previous
#include <cuda_runtime.h>
#include <cuda_bf16.h>
#include <math.h>
#include <stdint.h>

// ---------------------------------------------------------------------------
// Problem constants
// ---------------------------------------------------------------------------
#define BATCH   2
#define NSEQ    2048
#define DMODEL  1024
#define HEADS   16
#define DH      64
#define INNER   1024
#define NROWS   (BATCH*NSEQ)   // 4096
#define SCALE   0.125f
#define LN_EPS  1e-5f

// ---------------------------------------------------------------------------
// Scratch (__device__ globals; no allocs allowed)
// ---------------------------------------------------------------------------
__device__ __nv_bfloat16 g_xn_h [(size_t)NROWS * DMODEL];
__device__ __nv_bfloat16 g_xn_l [(size_t)NROWS * DMODEL];
__device__ __nv_bfloat16 g_wq_h [(size_t)3*INNER * DMODEL];   // Wqkv^T [3072][1024]
__device__ __nv_bfloat16 g_wq_l [(size_t)3*INNER * DMODEL];
__device__ __nv_bfloat16 g_wo_h [(size_t)DMODEL * INNER];     // Wout^T
__device__ __nv_bfloat16 g_wo_l [(size_t)DMODEL * INNER];
__device__ __nv_bfloat16 g_qkv_h[(size_t)NROWS * 3 * INNER];  // bf16 hi QKV
__device__ __nv_bfloat16 g_qkv_l[(size_t)NROWS * 3 * INNER];  // bf16 lo QKV
__device__ __nv_bfloat16 g_ctx_h[(size_t)NROWS * INNER];
__device__ __nv_bfloat16 g_ctx_l[(size_t)NROWS * INNER];

// ---------------------------------------------------------------------------
// Helpers
// ---------------------------------------------------------------------------
__device__ __forceinline__ void split1(float v, __nv_bfloat16& h, __nv_bfloat16& l) {
    h = __float2bfloat16(v);
    l = __float2bfloat16(v - __bfloat162float(h));
}

__device__ __forceinline__ void ldsm4(uint32_t* r, uint32_t addr) {
    asm volatile("ldmatrix.sync.aligned.m8n8.x4.shared.b16 {%0,%1,%2,%3}, [%4];"
                 : "=r"(r[0]), "=r"(r[1]), "=r"(r[2]), "=r"(r[3]) : "r"(addr));
}

__device__ __forceinline__ void ldsm4t(uint32_t* r, uint32_t addr) {
    asm volatile("ldmatrix.sync.aligned.m8n8.x4.trans.shared.b16 {%0,%1,%2,%3}, [%4];"
                 : "=r"(r[0]), "=r"(r[1]), "=r"(r[2]), "=r"(r[3]) : "r"(addr));
}

__device__ __forceinline__ void mma16816(float* d, const uint32_t* a,
                                         const uint32_t* b) {
    asm volatile(
        "mma.sync.aligned.m16n8k16.row.col.f32.bf16.bf16.f32 "
        "{%0,%1,%2,%3}, {%4,%5,%6,%7}, {%8,%9}, {%0,%1,%2,%3};"
        : "+f"(d[0]), "+f"(d[1]), "+f"(d[2]), "+f"(d[3])
        : "r"(a[0]), "r"(a[1]), "r"(a[2]), "r"(a[3]), "r"(b[0]), "r"(b[1]));
}

__device__ __forceinline__ void cp16(uint32_t dst, const void* src) {
    asm volatile("cp.async.cg.shared.global [%0], [%1], 16;"
                 :: "r"(dst), "l"(__cvta_generic_to_global(src)));
}

__device__ __forceinline__ uint32_t packbf2(float a, float b) {
    __nv_bfloat162 t = __floats2bfloat162_rn(a, b);
    return *(uint32_t*)&t;
}

// ---------------------------------------------------------------------------
// Kernel 1: LayerNorm fused with bf16 hi/lo split output
// ---------------------------------------------------------------------------
__global__ __launch_bounds__(256) void ln_kernel(
    const float* __restrict__ x, const float* __restrict__ gamma,
    const float* __restrict__ beta,
    __nv_bfloat16* __restrict__ xh, __nv_bfloat16* __restrict__ xl)
{
    int row = blockIdx.x;
    int tid = threadIdx.x;
    const float4* xr = (const float4*)(x + (size_t)row * DMODEL);
    float4 v = xr[tid];

    float s  = v.x + v.y + v.z + v.w;
    float ss = v.x*v.x + v.y*v.y + v.z*v.z + v.w*v.w;
    #pragma unroll
    for (int off = 16; off; off >>= 1) {
        s  += __shfl_xor_sync(0xffffffffu, s,  off);
        ss += __shfl_xor_sync(0xffffffffu, ss, off);
    }
    __shared__ float sbuf[8], ssbuf[8];
    int warp = tid >> 5, lane = tid & 31;
    if (lane == 0) { sbuf[warp] = s; ssbuf[warp] = ss; }
    __syncthreads();
    s = 0.f; ss = 0.f;
    #pragma unroll
    for (int w = 0; w < 8; w++) { s += sbuf[w]; ss += ssbuf[w]; }

    float mu  = s * (1.0f / DMODEL);
    float var = ss * (1.0f / DMODEL) - mu * mu;
    float inv = rsqrtf(var + LN_EPS);

    float4 g  = ((const float4*)gamma)[tid];
    float4 be = ((const float4*)beta)[tid];
    float o0 = (v.x - mu) * inv * g.x + be.x;
    float o1 = (v.y - mu) * inv * g.y + be.y;
    float o2 = (v.z - mu) * inv * g.z + be.z;
    float o3 = (v.w - mu) * inv * g.w + be.w;

    __nv_bfloat16 h0,h1,h2,h3,l0,l1,l2,l3;
    split1(o0,h0,l0); split1(o1,h1,l1); split1(o2,h2,l2); split1(o3,h3,l3);
    size_t off = (size_t)row * DMODEL + tid * 4;
    ushort4 hv = { __bfloat16_as_ushort(h0), __bfloat16_as_ushort(h1),
                   __bfloat16_as_ushort(h2), __bfloat16_as_ushort(h3) };
    ushort4 lv = { __bfloat16_as_ushort(l0), __bfloat16_as_ushort(l1),
                   __bfloat16_as_ushort(l2), __bfloat16_as_ushort(l3) };
    *(ushort4*)(xh + off) = hv;
    *(ushort4*)(xl + off) = lv;
}

// ---------------------------------------------------------------------------
// Kernel 2: transpose + bf16 split for weights
// ---------------------------------------------------------------------------
__global__ __launch_bounds__(256) void splitT_kernel(
    const float* __restrict__ W,
    __nv_bfloat16* __restrict__ Th, __nv_bfloat16* __restrict__ Tl,
    int K, int N)
{
    __shared__ float t[32][33];
    int n0 = blockIdx.x * 32, k0 = blockIdx.y * 32;
    int tx = threadIdx.x, ty = threadIdx.y;
    #pragma unroll
    for (int j = 0; j < 4; j++) {
        int r = ty + j * 8;
        t[r][tx] = W[(size_t)(k0 + r) * N + n0 + tx];
    }
    __syncthreads();
    #pragma unroll
    for (int j = 0; j < 4; j++) {
        int r = ty + j * 8;
        float v = t[tx][r];
        __nv_bfloat16 h, l;
        split1(v, h, l);
        size_t o = (size_t)(n0 + r) * K + k0 + tx;
        Th[o] = h; Tl[o] = l;
    }
}

// ---------------------------------------------------------------------------
// Kernel 3: bf16x3-split GEMM on mma.sync. Epilogue: fp32 OR bf16 hi/lo.
// ---------------------------------------------------------------------------
#define GK      1024
#define GBK     32
#define GSTRIDE 40
#define GBUF    (128 * GSTRIDE)
#define GSMEM   (8 * GBUF * 2)

__global__ __launch_bounds__(256) void mma_gemm(
    const __nv_bfloat16* __restrict__ Ah, const __nv_bfloat16* __restrict__ Al,
    const __nv_bfloat16* __restrict__ Bh, const __nv_bfloat16* __restrict__ Bl,
    float* __restrict__ Cf,
    __nv_bfloat16* __restrict__ Ch, __nv_bfloat16* __restrict__ Cl,
    int N)
{
    extern __shared__ __nv_bfloat16 smg[];
    __nv_bfloat16* sAh = smg;
    __nv_bfloat16* sAl = smg + 2 * GBUF;
    __nv_bfloat16* sBh = smg + 4 * GBUF;
    __nv_bfloat16* sBl = smg + 6 * GBUF;

    const int tid  = threadIdx.x;
    const int lane = tid & 31, wid = tid >> 5;
    const int wm = wid >> 2, wn = wid & 3;
    const int m0 = blockIdx.y * 128, n0 = blockIdx.x * 128;

    const uint32_t uAh = (uint32_t)__cvta_generic_to_shared(sAh);
    const uint32_t uAl = (uint32_t)__cvta_generic_to_shared(sAl);
    const uint32_t uBh = (uint32_t)__cvta_generic_to_shared(sBh);
    const uint32_t uBl = (uint32_t)__cvta_generic_to_shared(sBl);

    const int cr0 = (tid)        >> 2, cs0 = (tid)        & 3;
    const int cr1 = (tid + 256)  >> 2, cs1 = (tid + 256)  & 3;

    float acc[4][4][4];
    #pragma unroll
    for (int f = 0; f < 4; f++)
        #pragma unroll
        for (int j = 0; j < 4; j++)
            #pragma unroll
            for (int e = 0; e < 4; e++) acc[f][j][e] = 0.f;

    const uint32_t aoff = ((uint32_t)((wm*64 + (lane & 15)) * GSTRIDE
                          + (lane >> 4) * 8)) * 2;
    const uint32_t boff = ((uint32_t)((wn*32 + (lane & 7) + ((lane >> 4) << 3)) * GSTRIDE
                          + ((lane >> 3) & 1) * 8)) * 2;

#define STAGE_COPY(stage, kc)                                                   \
    do {                                                                        \
        uint32_t so = (uint32_t)(stage) * GBUF * 2;                             \
        uint32_t d0 = (uint32_t)(cr0 * GSTRIDE + cs0 * 8) * 2 + so;             \
        uint32_t d1 = (uint32_t)(cr1 * GSTRIDE + cs1 * 8) * 2 + so;             \
        size_t ga0 = (size_t)(m0 + cr0) * GK + (kc) + cs0 * 8;                  \
        size_t ga1 = (size_t)(m0 + cr1) * GK + (kc) + cs1 * 8;                  \
        size_t gb0 = (size_t)(n0 + cr0) * GK + (kc) + cs0 * 8;                  \
        size_t gb1 = (size_t)(n0 + cr1) * GK + (kc) + cs1 * 8;                  \
        cp16(uAh + d0, Ah + ga0); cp16(uAh + d1, Ah + ga1);                     \
        cp16(uAl + d0, Al + ga0); cp16(uAl + d1, Al + ga1);                     \
        cp16(uBh + d0, Bh + gb0); cp16(uBh + d1, Bh + gb1);                     \
        cp16(uBl + d0, Bl + gb0); cp16(uBl + d1, Bl + gb1);                     \
    } while (0)

    STAGE_COPY(0, 0);
    asm volatile("cp.async.commit_group;" ::: "memory");

    const int nk = GK / GBK;
    for (int kt = 0; kt < nk; kt++) {
        const int stage = kt & 1;
        if (kt + 1 < nk) {
            STAGE_COPY(stage ^ 1, (kt + 1) * GBK);
            asm volatile("cp.async.commit_group;" ::: "memory");
            asm volatile("cp.async.wait_group 1;" ::: "memory");
        } else {
            asm volatile("cp.async.wait_group 0;" ::: "memory");
        }
        __syncthreads();

        const uint32_t so = (uint32_t)stage * GBUF * 2;
        #pragma unroll
        for (int ks = 0; ks < 2; ks++) {
            uint32_t ah[4][4], al[4][4], bh[2][4], bl[2][4];
            #pragma unroll
            for (int f = 0; f < 4; f++) {
                uint32_t o = so + aoff + (uint32_t)(f * 16 * GSTRIDE + ks * 16) * 2;
                ldsm4(ah[f], uAh + o);
                ldsm4(al[f], uAl + o);
            }
            #pragma unroll
            for (int p = 0; p < 2; p++) {
                uint32_t o = so + boff + (uint32_t)(p * 16 * GSTRIDE + ks * 16) * 2;
                ldsm4(bh[p], uBh + o);
                ldsm4(bl[p], uBl + o);
            }
            #pragma unroll
            for (int f = 0; f < 4; f++) {
                #pragma unroll
                for (int j = 0; j < 4; j++) {
                    const int p = j >> 1, sub = (j & 1) * 2;
                    uint32_t bhp[2] = { bh[p][sub], bh[p][sub + 1] };
                    uint32_t blp[2] = { bl[p][sub], bl[p][sub + 1] };
                    mma16816(acc[f][j], ah[f], bhp);
                    mma16816(acc[f][j], ah[f], blp);
                    mma16816(acc[f][j], al[f], bhp);
                }
            }
        }
        __syncthreads();
    }

    const int erow = m0 + wm * 64 + (lane >> 2);
    const int ecol = n0 + wn * 32 + (lane & 3) * 2;
    if (Cf) {
        #pragma unroll
        for (int f = 0; f < 4; f++) {
            #pragma unroll
            for (int j = 0; j < 4; j++) {
                float* d0 = Cf + (size_t)(erow + f * 16)     * N + ecol + j * 8;
                float* d1 = Cf + (size_t)(erow + f * 16 + 8) * N + ecol + j * 8;
                *(float2*)d0 = make_float2(acc[f][j][0], acc[f][j][1]);
                *(float2*)d1 = make_float2(acc[f][j][2], acc[f][j][3]);
            }
        }
    } else {
        #pragma unroll
        for (int f = 0; f < 4; f++) {
            #pragma unroll
            for (int j = 0; j < 4; j++) {
                #pragma unroll
                for (int half = 0; half < 2; half++) {
                    size_t o = (size_t)(erow + f*16 + half*8) * N + ecol + j*8;
                    float v0 = acc[f][j][half*2], v1 = acc[f][j][half*2 + 1];
                    __nv_bfloat16 h0,l0,h1,l1;
                    split1(v0,h0,l0); split1(v1,h1,l1);
                    ushort2 hv = { __bfloat16_as_ushort(h0), __bfloat16_as_ushort(h1) };
                    ushort2 lv = { __bfloat16_as_ushort(l0), __bfloat16_as_ushort(l1) };
                    *(ushort2*)(Ch + o) = hv;
                    *(ushort2*)(Cl + o) = lv;
                }
            }
        }
    }
#undef STAGE_COPY
}

// ---------------------------------------------------------------------------
// Kernel 4: flash attention on mma.sync, bf16x3 split throughout.
// BQ=128, BK=64, 8 warps x 16 q-rows. grid (16, HEADS, BATCH).
// ---------------------------------------------------------------------------
#define AST   72                         // smem row stride (bf16 elems)
#define AQB   (128 * AST * 2)            // bytes, one Q array
#define AKB   (64 * AST * 2)             // bytes, one K/V array (9216)
#define AKVST (4 * AKB)                  // bytes per KV stage (36864)
#define ASMEM (2 * AQB + 2 * AKVST)      // 36864 + 73728 = 110592

__global__ __launch_bounds__(256) void attn_mma_kernel(
    const __nv_bfloat16* __restrict__ qh_g, const __nv_bfloat16* __restrict__ ql_g,
    const float* __restrict__ mask,
    __nv_bfloat16* __restrict__ ctxh, __nv_bfloat16* __restrict__ ctxl)
{
    extern __shared__ char sma[];
    const uint32_t uQh = (uint32_t)__cvta_generic_to_shared(sma);
    const uint32_t uQl = uQh + AQB;
    const uint32_t uKV = uQh + 2 * AQB;

    const int tid = threadIdx.x, lane = tid & 31, wq = tid >> 5;
    const int qt = blockIdx.x, h = blockIdx.y, b = blockIdx.z;
    const int q0 = qt * 128;
    const size_t rowbase = (size_t)b * NSEQ;
    const size_t qkstride = 3 * INNER;

    // ---- issue Q copy + KV stage 0
    {
        #pragma unroll
        for (int t = 0; t < 4; t++) {                 // Q: 1024 chunks / 256
            int idx = tid + t * 256;
            int r = idx >> 3, c = idx & 7;
            uint32_t d = (uint32_t)(r * AST + c * 8) * 2;
            size_t g = (rowbase + q0 + r) * qkstride + h * DH + c * 8;
            cp16(uQh + d, qh_g + g);
            cp16(uQl + d, ql_g + g);
        }
    }
#define KV_COPY(stage, kc)                                                     \
    do {                                                                       \
        uint32_t so = uKV + (uint32_t)(stage) * AKVST;                         \
        _Pragma("unroll")                                                      \
        for (int t = 0; t < 2; t++) {                                          \
            int idx = tid + t * 256;                                           \
            int r = idx >> 3, c = idx & 7;                                     \
            uint32_t d = (uint32_t)(r * AST + c * 8) * 2;                      \
            size_t gk = (rowbase + (kc) + r) * qkstride + INNER   + h*DH + c*8;\
            size_t gv = (rowbase + (kc) + r) * qkstride + 2*INNER + h*DH + c*8;\
            cp16(so + d,           qh_g + gk);                                 \
            cp16(so + AKB + d,     ql_g + gk);                                 \
            cp16(so + 2*AKB + d,   qh_g + gv);                                 \
            cp16(so + 3*AKB + d,   ql_g + gv);                                 \
        }                                                                      \
    } while (0)

    KV_COPY(0, 0);
    asm volatile("cp.async.commit_group;" ::: "memory");

    uint32_t qfh[4][4], qfl[4][4];
    float oacc[8][4];
    #pragma unroll
    for (int j = 0; j < 8; j++)
        #pragma unroll
        for (int e = 0; e < 4; e++) oacc[j][e] = 0.f;
    float rmax0 = -1e30f, rmax1 = -1e30f, rsum0 = 0.f, rsum1 = 0.f;

    const int nk = NSEQ / 64;   // 32
    for (int kt = 0; kt < nk; kt++) {
        const int stage = kt & 1;
        if (kt + 1 < nk) {
            KV_COPY(stage ^ 1, (kt + 1) * 64);
            asm volatile("cp.async.commit_group;" ::: "memory");
            asm volatile("cp.async.wait_group 1;" ::: "memory");
        } else {
            asm volatile("cp.async.wait_group 0;" ::: "memory");
        }
        __syncthreads();

        if (kt == 0) {
            // Q fragments (register-resident for the whole kernel)
            #pragma unroll
            for (int kk = 0; kk < 4; kk++) {
                uint32_t o = (uint32_t)((wq*16 + (lane & 15)) * AST
                             + (lane >> 4) * 8 + kk * 16) * 2;
                ldsm4(qfh[kk], uQh + o);
                ldsm4(qfl[kk], uQl + o);
            }
        }

        const uint32_t sK = uKV + (uint32_t)stage * AKVST;
        const uint32_t sV = sK + 2 * AKB;

        // ---- S = Q K^T (3-term)
        float sacc[8][4];
        #pragma unroll
        for (int j = 0; j < 8; j++)
            #pragma unroll
            for (int e = 0; e < 4; e++) sacc[j][e] = 0.f;

        #pragma unroll
        for (int kk = 0; kk < 4; kk++) {
            uint32_t kbh[4][4], kbl[4][4];
            #pragma unroll
            for (int jb = 0; jb < 4; jb++) {
                uint32_t o = (uint32_t)((jb*16 + (lane & 7) + ((lane >> 4) << 3)) * AST
                             + ((lane >> 3) & 1) * 8 + kk * 16) * 2;
                ldsm4(kbh[jb], sK + o);
                ldsm4(kbl[jb], sK + AKB + o);
            }
            #pragma unroll
            for (int jb = 0; jb < 4; jb++) {
                #pragma unroll
                for (int sub = 0; sub < 2; sub++) {
                    int j = jb * 2 + sub;
                    uint32_t bh[2] = { kbh[jb][sub*2], kbh[jb][sub*2+1] };
                    uint32_t bl[2] = { kbl[jb][sub*2], kbl[jb][sub*2+1] };
                    mma16816(sacc[j], qfh[kk], bh);
                    mma16816(sacc[j], qfh[kk], bl);
                    mma16816(sacc[j], qfl[kk], bh);
                }
            }
        }

        // ---- mask add (before scale), then scale
        {
            const int qrow = q0 + wq * 16 + (lane >> 2);
            const int kcol = kt * 64 + (lane & 3) * 2;
            const float* mg = mask + ((size_t)b * NSEQ + qrow) * NSEQ + kcol;
            #pragma unroll
            for (int j = 0; j < 8; j++) {
                float2 m0 = *(const float2*)(mg + j * 8);
                float2 m1 = *(const float2*)(mg + 8 * NSEQ + j * 8);
                sacc[j][0] = (sacc[j][0] + m0.x) * SCALE;
                sacc[j][1] = (sacc[j][1] + m0.y) * SCALE;
                sacc[j][2] = (sacc[j][2] + m1.x) * SCALE;
                sacc[j][3] = (sacc[j][3] + m1.y) * SCALE;
            }
        }

        // ---- online softmax (rows lane>>2 and +8 of this warp's 16)
        float tm0 = -1e30f, tm1 = -1e30f;
        #pragma unroll
        for (int j = 0; j < 8; j++) {
            tm0 = fmaxf(tm0, fmaxf(sacc[j][0], sacc[j][1]));
            tm1 = fmaxf(tm1, fmaxf(sacc[j][2], sacc[j][3]));
        }
        #pragma unroll
        for (int off = 1; off <= 2; off <<= 1) {
            tm0 = fmaxf(tm0, __shfl_xor_sync(0xffffffffu, tm0, off));
            tm1 = fmaxf(tm1, __shfl_xor_sync(0xffffffffu, tm1, off));
        }
        float nm0 = fmaxf(rmax0, tm0), nm1 = fmaxf(rmax1, tm1);
        float corr0 = __expf(rmax0 - nm0), corr1 = __expf(rmax1 - nm1);
        rmax0 = nm0; rmax1 = nm1;

        float ps0 = 0.f, ps1 = 0.f;
        #pragma unroll
        for (int j = 0; j < 8; j++) {
            sacc[j][0] = __expf(sacc[j][0] - nm0);
            sacc[j][1] = __expf(sacc[j][1] - nm0);
            sacc[j][2] = __expf(sacc[j][2] - nm1);
            sacc[j][3] = __expf(sacc[j][3] - nm1);
            ps0 += sacc[j][0] + sacc[j][1];
            ps1 += sacc[j][2] + sacc[j][3];
        }
        #pragma unroll
        for (int off = 1; off <= 2; off <<= 1) {
            ps0 += __shfl_xor_sync(0xffffffffu, ps0, off);
            ps1 += __shfl_xor_sync(0xffffffffu, ps1, off);
        }
        rsum0 = rsum0 * corr0 + ps0;
        rsum1 = rsum1 * corr1 + ps1;

        // rescale O
        #pragma unroll
        for (int j = 0; j < 8; j++) {
            oacc[j][0] *= corr0; oacc[j][1] *= corr0;
            oacc[j][2] *= corr1; oacc[j][3] *= corr1;
        }

        // ---- pack P into A fragments (hi/lo)
        uint32_t pah[4][4], pal[4][4];
        #pragma unroll
        for (int kp = 0; kp < 4; kp++) {
            const int j0 = kp * 2, j1 = kp * 2 + 1;
            float p00 = sacc[j0][0], p01 = sacc[j0][1];
            float p02 = sacc[j0][2], p03 = sacc[j0][3];
            float p10 = sacc[j1][0], p11 = sacc[j1][1];
            float p12 = sacc[j1][2], p13 = sacc[j1][3];
            pah[kp][0] = packbf2(p00, p01);
            pah[kp][1] = packbf2(p02, p03);
            pah[kp][2] = packbf2(p10, p11);
            pah[kp][3] = packbf2(p12, p13);
            __nv_bfloat162* hp;
            hp = (__nv_bfloat162*)&pah[kp][0];
            pal[kp][0] = packbf2(p00 - __bfloat162float(hp->x), p01 - __bfloat162float(hp->y));
            hp = (__nv_bfloat162*)&pah[kp][1];
            pal[kp][1] = packbf2(p02 - __bfloat162float(hp->x), p03 - __bfloat162float(hp->y));
            hp = (__nv_bfloat162*)&pah[kp][2];
            pal[kp][2] = packbf2(p10 - __bfloat162float(hp->x), p11 - __bfloat162float(hp->y));
            hp = (__nv_bfloat162*)&pah[kp][3];
            pal[kp][3] = packbf2(p12 - __bfloat162float(hp->x), p13 - __bfloat162float(hp->y));
        }

        // ---- O += P V (3-term), V fragments via ldmatrix.trans
        #pragma unroll
        for (int kp = 0; kp < 4; kp++) {
            uint32_t vbh[4][4], vbl[4][4];
            #pragma unroll
            for (int db = 0; db < 4; db++) {
                uint32_t o = (uint32_t)((kp*16 + (lane & 15)) * AST
                             + (lane >> 4) * 8 + db * 16) * 2;
                ldsm4t(vbh[db], sV + o);
                ldsm4t(vbl[db], sV + AKB + o);
            }
            #pragma unroll
            for (int db = 0; db < 4; db++) {
                #pragma unroll
                for (int sub = 0; sub < 2; sub++) {
                    int j = db * 2 + sub;
                    uint32_t bh[2] = { vbh[db][sub*2], vbh[db][sub*2+1] };
                    uint32_t bl[2] = { vbl[db][sub*2], vbl[db][sub*2+1] };
                    mma16816(oacc[j], pah[kp], bh);
                    mma16816(oacc[j], pah[kp], bl);
                    mma16816(oacc[j], pal[kp], bh);
                }
            }
        }
        __syncthreads();
    }
#undef KV_COPY

    // ---- normalize + write ctx (bf16 hi/lo)
    const float inv0 = 1.0f / rsum0, inv1 = 1.0f / rsum1;
    const int row0 = q0 + wq * 16 + (lane >> 2);
    #pragma unroll
    for (int j = 0; j < 8; j++) {
        const int col = h * DH + j * 8 + (lane & 3) * 2;
        float v0 = oacc[j][0] * inv0, v1 = oacc[j][1] * inv0;
        float v2 = oacc[j][2] * inv1, v3 = oacc[j][3] * inv1;
        __nv_bfloat16 h0,l0,h1,l1,h2,l2,h3,l3;
        split1(v0,h0,l0); split1(v1,h1,l1); split1(v2,h2,l2); split1(v3,h3,l3);
        size_t o0 = (rowbase + row0)     * (size_t)INNER + col;
        size_t o1 = (rowbase + row0 + 8) * (size_t)INNER + col;
        ushort2 a0 = { __bfloat16_as_ushort(h0), __bfloat16_as_ushort(h1) };
        ushort2 b0 = { __bfloat16_as_ushort(l0), __bfloat16_as_ushort(l1) };
        ushort2 a1 = { __bfloat16_as_ushort(h2), __bfloat16_as_ushort(h3) };
        ushort2 b1 = { __bfloat16_as_ushort(l2), __bfloat16_as_ushort(l3) };
        *(ushort2*)(ctxh + o0) = a0;
        *(ushort2*)(ctxl + o0) = b0;
        *(ushort2*)(ctxh + o1) = a1;
        *(ushort2*)(ctxl + o1) = b1;
    }
}

// ---------------------------------------------------------------------------
// launch
// ---------------------------------------------------------------------------
extern "C" void kernel_launch(void* const* d_in, const int* in_sizes, int n_in,
                              void* d_out, int out_size)
{
    const float* x     = (const float*)d_in[0];
    const float* m     = (const float*)d_in[1];
    const float* gamma = (const float*)d_in[2];
    const float* beta  = (const float*)d_in[3];
    const float* Wqkv  = (const float*)d_in[4];
    const float* Wout  = (const float*)d_in[5];
    float* out = (float*)d_out;

    __nv_bfloat16 *xnh, *xnl, *wqh, *wql, *woh, *wol, *qkvh, *qkvl, *ctxh, *ctxl;
    cudaGetSymbolAddress((void**)&xnh,  g_xn_h);
    cudaGetSymbolAddress((void**)&xnl,  g_xn_l);
    cudaGetSymbolAddress((void**)&wqh,  g_wq_h);
    cudaGetSymbolAddress((void**)&wql,  g_wq_l);
    cudaGetSymbolAddress((void**)&woh,  g_wo_h);
    cudaGetSymbolAddress((void**)&wol,  g_wo_l);
    cudaGetSymbolAddress((void**)&qkvh, g_qkv_h);
    cudaGetSymbolAddress((void**)&qkvl, g_qkv_l);
    cudaGetSymbolAddress((void**)&ctxh, g_ctx_h);
    cudaGetSymbolAddress((void**)&ctxl, g_ctx_l);

    cudaFuncSetAttribute(mma_gemm,
                         cudaFuncAttributeMaxDynamicSharedMemorySize, GSMEM);
    cudaFuncSetAttribute(attn_mma_kernel,
                         cudaFuncAttributeMaxDynamicSharedMemorySize, ASMEM);

    // 1. LayerNorm (+ bf16 split)
    ln_kernel<<<NROWS, 256>>>(x, gamma, beta, xnh, xnl);

    // 2. weight transpose + split
    splitT_kernel<<<dim3(3*INNER/32, DMODEL/32), dim3(32,8)>>>(Wqkv, wqh, wql, DMODEL, 3*INNER);
    splitT_kernel<<<dim3(DMODEL/32,  INNER/32),  dim3(32,8)>>>(Wout, woh, wol, INNER, DMODEL);

    // 3. QKV projection -> bf16 hi/lo qkv
    mma_gemm<<<dim3(3*INNER/128, NROWS/128), 256, GSMEM>>>(
        xnh, xnl, wqh, wql, nullptr, qkvh, qkvl, 3*INNER);

    // 4. masked flash attention on tensor cores
    attn_mma_kernel<<<dim3(NSEQ/128, HEADS, BATCH), 256, ASMEM>>>(
        qkvh, qkvl, m, ctxh, ctxl);

    // 5. output projection -> fp32 out
    mma_gemm<<<dim3(DMODEL/128, NROWS/128), 256, GSMEM>>>(
        ctxh, ctxl, woh, wol, out, nullptr, nullptr, DMODEL);
}

// round 8
// speedup vs baseline: 2.7692x; 1.1631x over previous
#include <cuda_runtime.h>
#include <cuda_bf16.h>
#include <math.h>
#include <stdint.h>

// ---------------------------------------------------------------------------
// Problem constants
// ---------------------------------------------------------------------------
#define BATCH   2
#define NSEQ    2048
#define DMODEL  1024
#define HEADS   16
#define DH      64
#define INNER   1024
#define NROWS   (BATCH*NSEQ)   // 4096
#define SCALE   0.125f
#define LN_EPS  1e-5f

// ---------------------------------------------------------------------------
// Scratch (__device__ globals; no allocs allowed)
// ---------------------------------------------------------------------------
__device__ __nv_bfloat16 g_xn_h [(size_t)NROWS * DMODEL];
__device__ __nv_bfloat16 g_xn_l [(size_t)NROWS * DMODEL];
__device__ __nv_bfloat16 g_wq_h [(size_t)3*INNER * DMODEL];   // Wqkv^T [3072][1024]
__device__ __nv_bfloat16 g_wq_l [(size_t)3*INNER * DMODEL];
__device__ __nv_bfloat16 g_wo_h [(size_t)DMODEL * INNER];     // Wout^T
__device__ __nv_bfloat16 g_wo_l [(size_t)DMODEL * INNER];
__device__ __nv_bfloat16 g_qkv_h[(size_t)NROWS * 3 * INNER];  // bf16 hi QKV
__device__ __nv_bfloat16 g_qkv_l[(size_t)NROWS * 3 * INNER];  // bf16 lo QKV
__device__ __nv_bfloat16 g_ctx_h[(size_t)NROWS * INNER];
__device__ __nv_bfloat16 g_ctx_l[(size_t)NROWS * INNER];

// ---------------------------------------------------------------------------
// Helpers
// ---------------------------------------------------------------------------
__device__ __forceinline__ void split1(float v, __nv_bfloat16& h, __nv_bfloat16& l) {
    h = __float2bfloat16(v);
    l = __float2bfloat16(v - __bfloat162float(h));
}

__device__ __forceinline__ void ldsm4(uint32_t* r, uint32_t addr) {
    asm volatile("ldmatrix.sync.aligned.m8n8.x4.shared.b16 {%0,%1,%2,%3}, [%4];"
                 : "=r"(r[0]), "=r"(r[1]), "=r"(r[2]), "=r"(r[3]) : "r"(addr));
}

__device__ __forceinline__ void ldsm4t(uint32_t* r, uint32_t addr) {
    asm volatile("ldmatrix.sync.aligned.m8n8.x4.trans.shared.b16 {%0,%1,%2,%3}, [%4];"
                 : "=r"(r[0]), "=r"(r[1]), "=r"(r[2]), "=r"(r[3]) : "r"(addr));
}

__device__ __forceinline__ void mma16816(float* d, const uint32_t* a,
                                         const uint32_t* b) {
    asm volatile(
        "mma.sync.aligned.m16n8k16.row.col.f32.bf16.bf16.f32 "
        "{%0,%1,%2,%3}, {%4,%5,%6,%7}, {%8,%9}, {%0,%1,%2,%3};"
        : "+f"(d[0]), "+f"(d[1]), "+f"(d[2]), "+f"(d[3])
        : "r"(a[0]), "r"(a[1]), "r"(a[2]), "r"(a[3]), "r"(b[0]), "r"(b[1]));
}

__device__ __forceinline__ void cp16(uint32_t dst, const void* src) {
    asm volatile("cp.async.cg.shared.global [%0], [%1], 16;"
                 :: "r"(dst), "l"(__cvta_generic_to_global(src)));
}

__device__ __forceinline__ uint32_t packbf2(float a, float b) {
    __nv_bfloat162 t = __floats2bfloat162_rn(a, b);
    return *(uint32_t*)&t;
}

// ---------------------------------------------------------------------------
// Kernel 1: LayerNorm fused with bf16 hi/lo split output
// ---------------------------------------------------------------------------
__global__ __launch_bounds__(256) void ln_kernel(
    const float* __restrict__ x, const float* __restrict__ gamma,
    const float* __restrict__ beta,
    __nv_bfloat16* __restrict__ xh, __nv_bfloat16* __restrict__ xl)
{
    int row = blockIdx.x;
    int tid = threadIdx.x;
    const float4* xr = (const float4*)(x + (size_t)row * DMODEL);
    float4 v = xr[tid];

    float s  = v.x + v.y + v.z + v.w;
    float ss = v.x*v.x + v.y*v.y + v.z*v.z + v.w*v.w;
    #pragma unroll
    for (int off = 16; off; off >>= 1) {
        s  += __shfl_xor_sync(0xffffffffu, s,  off);
        ss += __shfl_xor_sync(0xffffffffu, ss, off);
    }
    __shared__ float sbuf[8], ssbuf[8];
    int warp = tid >> 5, lane = tid & 31;
    if (lane == 0) { sbuf[warp] = s; ssbuf[warp] = ss; }
    __syncthreads();
    s = 0.f; ss = 0.f;
    #pragma unroll
    for (int w = 0; w < 8; w++) { s += sbuf[w]; ss += ssbuf[w]; }

    float mu  = s * (1.0f / DMODEL);
    float var = ss * (1.0f / DMODEL) - mu * mu;
    float inv = rsqrtf(var + LN_EPS);

    float4 g  = ((const float4*)gamma)[tid];
    float4 be = ((const float4*)beta)[tid];
    float o0 = (v.x - mu) * inv * g.x + be.x;
    float o1 = (v.y - mu) * inv * g.y + be.y;
    float o2 = (v.z - mu) * inv * g.z + be.z;
    float o3 = (v.w - mu) * inv * g.w + be.w;

    __nv_bfloat16 h0,h1,h2,h3,l0,l1,l2,l3;
    split1(o0,h0,l0); split1(o1,h1,l1); split1(o2,h2,l2); split1(o3,h3,l3);
    size_t off = (size_t)row * DMODEL + tid * 4;
    ushort4 hv = { __bfloat16_as_ushort(h0), __bfloat16_as_ushort(h1),
                   __bfloat16_as_ushort(h2), __bfloat16_as_ushort(h3) };
    ushort4 lv = { __bfloat16_as_ushort(l0), __bfloat16_as_ushort(l1),
                   __bfloat16_as_ushort(l2), __bfloat16_as_ushort(l3) };
    *(ushort4*)(xh + off) = hv;
    *(ushort4*)(xl + off) = lv;
}

// ---------------------------------------------------------------------------
// Kernel 2: transpose + bf16 split for weights
// ---------------------------------------------------------------------------
__global__ __launch_bounds__(256) void splitT_kernel(
    const float* __restrict__ W,
    __nv_bfloat16* __restrict__ Th, __nv_bfloat16* __restrict__ Tl,
    int K, int N)
{
    __shared__ float t[32][33];
    int n0 = blockIdx.x * 32, k0 = blockIdx.y * 32;
    int tx = threadIdx.x, ty = threadIdx.y;
    #pragma unroll
    for (int j = 0; j < 4; j++) {
        int r = ty + j * 8;
        t[r][tx] = W[(size_t)(k0 + r) * N + n0 + tx];
    }
    __syncthreads();
    #pragma unroll
    for (int j = 0; j < 4; j++) {
        int r = ty + j * 8;
        float v = t[tx][r];
        __nv_bfloat16 h, l;
        split1(v, h, l);
        size_t o = (size_t)(n0 + r) * K + k0 + tx;
        Th[o] = h; Tl[o] = l;
    }
}

// ---------------------------------------------------------------------------
// Kernel 3: bf16x3-split GEMM on mma.sync. Epilogue: fp32 OR bf16 hi/lo.
// 2 CTAs/SM target: __launch_bounds__(256,2), transient fragments.
// ---------------------------------------------------------------------------
#define GK      1024
#define GBK     32
#define GSTRIDE 40
#define GBUF    (128 * GSTRIDE)
#define GSMEM   (8 * GBUF * 2)

__global__ __launch_bounds__(256, 2) void mma_gemm(
    const __nv_bfloat16* __restrict__ Ah, const __nv_bfloat16* __restrict__ Al,
    const __nv_bfloat16* __restrict__ Bh, const __nv_bfloat16* __restrict__ Bl,
    float* __restrict__ Cf,
    __nv_bfloat16* __restrict__ Ch, __nv_bfloat16* __restrict__ Cl,
    int N)
{
    extern __shared__ __nv_bfloat16 smg[];
    __nv_bfloat16* sAh = smg;
    __nv_bfloat16* sAl = smg + 2 * GBUF;
    __nv_bfloat16* sBh = smg + 4 * GBUF;
    __nv_bfloat16* sBl = smg + 6 * GBUF;

    const int tid  = threadIdx.x;
    const int lane = tid & 31, wid = tid >> 5;
    const int wm = wid >> 2, wn = wid & 3;
    const int m0 = blockIdx.y * 128, n0 = blockIdx.x * 128;

    const uint32_t uAh = (uint32_t)__cvta_generic_to_shared(sAh);
    const uint32_t uAl = (uint32_t)__cvta_generic_to_shared(sAl);
    const uint32_t uBh = (uint32_t)__cvta_generic_to_shared(sBh);
    const uint32_t uBl = (uint32_t)__cvta_generic_to_shared(sBl);

    const int cr0 = (tid)        >> 2, cs0 = (tid)        & 3;
    const int cr1 = (tid + 256)  >> 2, cs1 = (tid + 256)  & 3;

    float acc[4][4][4];
    #pragma unroll
    for (int f = 0; f < 4; f++)
        #pragma unroll
        for (int j = 0; j < 4; j++)
            #pragma unroll
            for (int e = 0; e < 4; e++) acc[f][j][e] = 0.f;

    const uint32_t aoff = ((uint32_t)((wm*64 + (lane & 15)) * GSTRIDE
                          + (lane >> 4) * 8)) * 2;
    const uint32_t boff = ((uint32_t)((wn*32 + (lane & 7) + ((lane >> 4) << 3)) * GSTRIDE
                          + ((lane >> 3) & 1) * 8)) * 2;

#define STAGE_COPY(stage, kc)                                                   \
    do {                                                                        \
        uint32_t so = (uint32_t)(stage) * GBUF * 2;                             \
        uint32_t d0 = (uint32_t)(cr0 * GSTRIDE + cs0 * 8) * 2 + so;             \
        uint32_t d1 = (uint32_t)(cr1 * GSTRIDE + cs1 * 8) * 2 + so;             \
        size_t ga0 = (size_t)(m0 + cr0) * GK + (kc) + cs0 * 8;                  \
        size_t ga1 = (size_t)(m0 + cr1) * GK + (kc) + cs1 * 8;                  \
        size_t gb0 = (size_t)(n0 + cr0) * GK + (kc) + cs0 * 8;                  \
        size_t gb1 = (size_t)(n0 + cr1) * GK + (kc) + cs1 * 8;                  \
        cp16(uAh + d0, Ah + ga0); cp16(uAh + d1, Ah + ga1);                     \
        cp16(uAl + d0, Al + ga0); cp16(uAl + d1, Al + ga1);                     \
        cp16(uBh + d0, Bh + gb0); cp16(uBh + d1, Bh + gb1);                     \
        cp16(uBl + d0, Bl + gb0); cp16(uBl + d1, Bl + gb1);                     \
    } while (0)

    STAGE_COPY(0, 0);
    asm volatile("cp.async.commit_group;" ::: "memory");

    const int nk = GK / GBK;
    for (int kt = 0; kt < nk; kt++) {
        const int stage = kt & 1;
        if (kt + 1 < nk) {
            STAGE_COPY(stage ^ 1, (kt + 1) * GBK);
            asm volatile("cp.async.commit_group;" ::: "memory");
            asm volatile("cp.async.wait_group 1;" ::: "memory");
        } else {
            asm volatile("cp.async.wait_group 0;" ::: "memory");
        }
        __syncthreads();

        const uint32_t so = (uint32_t)stage * GBUF * 2;
        #pragma unroll
        for (int ks = 0; ks < 2; ks++) {
            uint32_t bh[2][4], bl[2][4];
            #pragma unroll
            for (int p = 0; p < 2; p++) {
                uint32_t o = so + boff + (uint32_t)(p * 16 * GSTRIDE + ks * 16) * 2;
                ldsm4(bh[p], uBh + o);
                ldsm4(bl[p], uBl + o);
            }
            #pragma unroll
            for (int f = 0; f < 4; f++) {
                uint32_t ah[4], al[4];
                uint32_t o = so + aoff + (uint32_t)(f * 16 * GSTRIDE + ks * 16) * 2;
                ldsm4(ah, uAh + o);
                ldsm4(al, uAl + o);
                #pragma unroll
                for (int j = 0; j < 4; j++) {
                    const int p = j >> 1, sub = (j & 1) * 2;
                    uint32_t bhp[2] = { bh[p][sub], bh[p][sub + 1] };
                    uint32_t blp[2] = { bl[p][sub], bl[p][sub + 1] };
                    mma16816(acc[f][j], ah, bhp);
                    mma16816(acc[f][j], ah, blp);
                    mma16816(acc[f][j], al, bhp);
                }
            }
        }
        __syncthreads();
    }

    const int erow = m0 + wm * 64 + (lane >> 2);
    const int ecol = n0 + wn * 32 + (lane & 3) * 2;
    if (Cf) {
        #pragma unroll
        for (int f = 0; f < 4; f++) {
            #pragma unroll
            for (int j = 0; j < 4; j++) {
                float* d0 = Cf + (size_t)(erow + f * 16)     * N + ecol + j * 8;
                float* d1 = Cf + (size_t)(erow + f * 16 + 8) * N + ecol + j * 8;
                *(float2*)d0 = make_float2(acc[f][j][0], acc[f][j][1]);
                *(float2*)d1 = make_float2(acc[f][j][2], acc[f][j][3]);
            }
        }
    } else {
        #pragma unroll
        for (int f = 0; f < 4; f++) {
            #pragma unroll
            for (int j = 0; j < 4; j++) {
                #pragma unroll
                for (int half = 0; half < 2; half++) {
                    size_t o = (size_t)(erow + f*16 + half*8) * N + ecol + j*8;
                    float v0 = acc[f][j][half*2], v1 = acc[f][j][half*2 + 1];
                    __nv_bfloat16 h0,l0,h1,l1;
                    split1(v0,h0,l0); split1(v1,h1,l1);
                    ushort2 hv = { __bfloat16_as_ushort(h0), __bfloat16_as_ushort(h1) };
                    ushort2 lv = { __bfloat16_as_ushort(l0), __bfloat16_as_ushort(l1) };
                    *(ushort2*)(Ch + o) = hv;
                    *(ushort2*)(Cl + o) = lv;
                }
            }
        }
    }
#undef STAGE_COPY
}

// ---------------------------------------------------------------------------
// Kernel 4: flash attention on mma.sync, bf16x3 split throughout.
// BQ=128, BK=64, 8 warps x 16 q-rows. grid (16, HEADS, BATCH).
// 2 CTAs/SM target: launch_bounds(256,2); Q fragments reloaded from smem.
// ---------------------------------------------------------------------------
#define AST   72                         // smem row stride (bf16 elems)
#define AQB   (128 * AST * 2)            // bytes, one Q array
#define AKB   (64 * AST * 2)             // bytes, one K/V array (9216)
#define AKVST (4 * AKB)                  // bytes per KV stage (36864)
#define ASMEM (2 * AQB + 2 * AKVST)      // 110592

__global__ __launch_bounds__(256, 2) void attn_mma_kernel(
    const __nv_bfloat16* __restrict__ qh_g, const __nv_bfloat16* __restrict__ ql_g,
    const float* __restrict__ mask,
    __nv_bfloat16* __restrict__ ctxh, __nv_bfloat16* __restrict__ ctxl)
{
    extern __shared__ char sma[];
    const uint32_t uQh = (uint32_t)__cvta_generic_to_shared(sma);
    const uint32_t uQl = uQh + AQB;
    const uint32_t uKV = uQh + 2 * AQB;

    const int tid = threadIdx.x, lane = tid & 31, wq = tid >> 5;
    const int qt = blockIdx.x, h = blockIdx.y, b = blockIdx.z;
    const int q0 = qt * 128;
    const size_t rowbase = (size_t)b * NSEQ;
    const size_t qkstride = 3 * INNER;

    // ---- issue Q copy + KV stage 0
    {
        #pragma unroll
        for (int t = 0; t < 4; t++) {
            int idx = tid + t * 256;
            int r = idx >> 3, c = idx & 7;
            uint32_t d = (uint32_t)(r * AST + c * 8) * 2;
            size_t g = (rowbase + q0 + r) * qkstride + h * DH + c * 8;
            cp16(uQh + d, qh_g + g);
            cp16(uQl + d, ql_g + g);
        }
    }
#define KV_COPY(stage, kc)                                                     \
    do {                                                                       \
        uint32_t so = uKV + (uint32_t)(stage) * AKVST;                         \
        _Pragma("unroll")                                                      \
        for (int t = 0; t < 2; t++) {                                          \
            int idx = tid + t * 256;                                           \
            int r = idx >> 3, c = idx & 7;                                     \
            uint32_t d = (uint32_t)(r * AST + c * 8) * 2;                      \
            size_t gk = (rowbase + (kc) + r) * qkstride + INNER   + h*DH + c*8;\
            size_t gv = (rowbase + (kc) + r) * qkstride + 2*INNER + h*DH + c*8;\
            cp16(so + d,           qh_g + gk);                                 \
            cp16(so + AKB + d,     ql_g + gk);                                 \
            cp16(so + 2*AKB + d,   qh_g + gv);                                 \
            cp16(so + 3*AKB + d,   ql_g + gv);                                 \
        }                                                                      \
    } while (0)

    KV_COPY(0, 0);
    asm volatile("cp.async.commit_group;" ::: "memory");

    float oacc[8][4];
    #pragma unroll
    for (int j = 0; j < 8; j++)
        #pragma unroll
        for (int e = 0; e < 4; e++) oacc[j][e] = 0.f;
    float rmax0 = -1e30f, rmax1 = -1e30f, rsum0 = 0.f, rsum1 = 0.f;

    // per-warp smem base offsets for fragment loads
    const uint32_t qoffb = (uint32_t)((wq*16 + (lane & 15)) * AST
                           + (lane >> 4) * 8) * 2;
    const uint32_t koffb = (uint32_t)(((lane & 7) + ((lane >> 4) << 3)) * AST
                           + ((lane >> 3) & 1) * 8) * 2;
    const uint32_t voffb = (uint32_t)(((lane & 15)) * AST + (lane >> 4) * 8) * 2;

    const int nk = NSEQ / 64;   // 32
    for (int kt = 0; kt < nk; kt++) {
        const int stage = kt & 1;
        if (kt + 1 < nk) {
            KV_COPY(stage ^ 1, (kt + 1) * 64);
            asm volatile("cp.async.commit_group;" ::: "memory");
            asm volatile("cp.async.wait_group 1;" ::: "memory");
        } else {
            asm volatile("cp.async.wait_group 0;" ::: "memory");
        }
        __syncthreads();

        const uint32_t sK = uKV + (uint32_t)stage * AKVST;
        const uint32_t sV = sK + 2 * AKB;

        // ---- S = Q K^T (3-term), fragments transient
        float sacc[8][4];
        #pragma unroll
        for (int j = 0; j < 8; j++)
            #pragma unroll
            for (int e = 0; e < 4; e++) sacc[j][e] = 0.f;

        #pragma unroll
        for (int kk = 0; kk < 4; kk++) {
            uint32_t qh[4], ql[4];
            ldsm4(qh, uQh + qoffb + (uint32_t)(kk * 16) * 2);
            ldsm4(ql, uQl + qoffb + (uint32_t)(kk * 16) * 2);
            #pragma unroll
            for (int jb = 0; jb < 4; jb++) {
                uint32_t kbh[4], kbl[4];
                uint32_t o = koffb + (uint32_t)(jb * 16 * AST + kk * 16) * 2;
                ldsm4(kbh, sK + o);
                ldsm4(kbl, sK + AKB + o);
                #pragma unroll
                for (int sub = 0; sub < 2; sub++) {
                    int j = jb * 2 + sub;
                    uint32_t bh[2] = { kbh[sub*2], kbh[sub*2+1] };
                    uint32_t bl[2] = { kbl[sub*2], kbl[sub*2+1] };
                    mma16816(sacc[j], qh, bh);
                    mma16816(sacc[j], qh, bl);
                    mma16816(sacc[j], ql, bh);
                }
            }
        }

        // ---- mask add (before scale), then scale
        {
            const int qrow = q0 + wq * 16 + (lane >> 2);
            const int kcol = kt * 64 + (lane & 3) * 2;
            const float* mg = mask + ((size_t)b * NSEQ + qrow) * NSEQ + kcol;
            #pragma unroll
            for (int j = 0; j < 8; j++) {
                float2 m0 = *(const float2*)(mg + j * 8);
                float2 m1 = *(const float2*)(mg + 8 * NSEQ + j * 8);
                sacc[j][0] = (sacc[j][0] + m0.x) * SCALE;
                sacc[j][1] = (sacc[j][1] + m0.y) * SCALE;
                sacc[j][2] = (sacc[j][2] + m1.x) * SCALE;
                sacc[j][3] = (sacc[j][3] + m1.y) * SCALE;
            }
        }

        // ---- online softmax
        float tm0 = -1e30f, tm1 = -1e30f;
        #pragma unroll
        for (int j = 0; j < 8; j++) {
            tm0 = fmaxf(tm0, fmaxf(sacc[j][0], sacc[j][1]));
            tm1 = fmaxf(tm1, fmaxf(sacc[j][2], sacc[j][3]));
        }
        #pragma unroll
        for (int off = 1; off <= 2; off <<= 1) {
            tm0 = fmaxf(tm0, __shfl_xor_sync(0xffffffffu, tm0, off));
            tm1 = fmaxf(tm1, __shfl_xor_sync(0xffffffffu, tm1, off));
        }
        float nm0 = fmaxf(rmax0, tm0), nm1 = fmaxf(rmax1, tm1);
        float corr0 = __expf(rmax0 - nm0), corr1 = __expf(rmax1 - nm1);
        rmax0 = nm0; rmax1 = nm1;

        float ps0 = 0.f, ps1 = 0.f;
        #pragma unroll
        for (int j = 0; j < 8; j++) {
            sacc[j][0] = __expf(sacc[j][0] - nm0);
            sacc[j][1] = __expf(sacc[j][1] - nm0);
            sacc[j][2] = __expf(sacc[j][2] - nm1);
            sacc[j][3] = __expf(sacc[j][3] - nm1);
            ps0 += sacc[j][0] + sacc[j][1];
            ps1 += sacc[j][2] + sacc[j][3];
        }
        #pragma unroll
        for (int off = 1; off <= 2; off <<= 1) {
            ps0 += __shfl_xor_sync(0xffffffffu, ps0, off);
            ps1 += __shfl_xor_sync(0xffffffffu, ps1, off);
        }
        rsum0 = rsum0 * corr0 + ps0;
        rsum1 = rsum1 * corr1 + ps1;

        #pragma unroll
        for (int j = 0; j < 8; j++) {
            oacc[j][0] *= corr0; oacc[j][1] *= corr0;
            oacc[j][2] *= corr1; oacc[j][3] *= corr1;
        }

        // ---- pack P into A fragments (hi/lo); sacc dies here
        uint32_t pah[4][4], pal[4][4];
        #pragma unroll
        for (int kp = 0; kp < 4; kp++) {
            const int j0 = kp * 2, j1 = kp * 2 + 1;
            float p00 = sacc[j0][0], p01 = sacc[j0][1];
            float p02 = sacc[j0][2], p03 = sacc[j0][3];
            float p10 = sacc[j1][0], p11 = sacc[j1][1];
            float p12 = sacc[j1][2], p13 = sacc[j1][3];
            pah[kp][0] = packbf2(p00, p01);
            pah[kp][1] = packbf2(p02, p03);
            pah[kp][2] = packbf2(p10, p11);
            pah[kp][3] = packbf2(p12, p13);
            __nv_bfloat162* hp;
            hp = (__nv_bfloat162*)&pah[kp][0];
            pal[kp][0] = packbf2(p00 - __bfloat162float(hp->x), p01 - __bfloat162float(hp->y));
            hp = (__nv_bfloat162*)&pah[kp][1];
            pal[kp][1] = packbf2(p02 - __bfloat162float(hp->x), p03 - __bfloat162float(hp->y));
            hp = (__nv_bfloat162*)&pah[kp][2];
            pal[kp][2] = packbf2(p10 - __bfloat162float(hp->x), p11 - __bfloat162float(hp->y));
            hp = (__nv_bfloat162*)&pah[kp][3];
            pal[kp][3] = packbf2(p12 - __bfloat162float(hp->x), p13 - __bfloat162float(hp->y));
        }

        // ---- O += P V (3-term), V fragments transient via ldmatrix.trans
        #pragma unroll
        for (int kp = 0; kp < 4; kp++) {
            #pragma unroll
            for (int db = 0; db < 4; db++) {
                uint32_t vbh[4], vbl[4];
                uint32_t o = voffb + (uint32_t)(kp * 16 * AST + db * 16) * 2;
                ldsm4t(vbh, sV + o);
                ldsm4t(vbl, sV + AKB + o);
                #pragma unroll
                for (int sub = 0; sub < 2; sub++) {
                    int j = db * 2 + sub;
                    uint32_t bh[2] = { vbh[sub*2], vbh[sub*2+1] };
                    uint32_t bl[2] = { vbl[sub*2], vbl[sub*2+1] };
                    mma16816(oacc[j], pah[kp], bh);
                    mma16816(oacc[j], pah[kp], bl);
                    mma16816(oacc[j], pal[kp], bh);
                }
            }
        }
        __syncthreads();
    }
#undef KV_COPY

    // ---- normalize + write ctx (bf16 hi/lo)
    const float inv0 = 1.0f / rsum0, inv1 = 1.0f / rsum1;
    const int row0 = q0 + wq * 16 + (lane >> 2);
    #pragma unroll
    for (int j = 0; j < 8; j++) {
        const int col = h * DH + j * 8 + (lane & 3) * 2;
        float v0 = oacc[j][0] * inv0, v1 = oacc[j][1] * inv0;
        float v2 = oacc[j][2] * inv1, v3 = oacc[j][3] * inv1;
        __nv_bfloat16 h0,l0,h1,l1,h2,l2,h3,l3;
        split1(v0,h0,l0); split1(v1,h1,l1); split1(v2,h2,l2); split1(v3,h3,l3);
        size_t o0 = (rowbase + row0)     * (size_t)INNER + col;
        size_t o1 = (rowbase + row0 + 8) * (size_t)INNER + col;
        ushort2 a0 = { __bfloat16_as_ushort(h0), __bfloat16_as_ushort(h1) };
        ushort2 b0 = { __bfloat16_as_ushort(l0), __bfloat16_as_ushort(l1) };
        ushort2 a1 = { __bfloat16_as_ushort(h2), __bfloat16_as_ushort(h3) };
        ushort2 b1 = { __bfloat16_as_ushort(l2), __bfloat16_as_ushort(l3) };
        *(ushort2*)(ctxh + o0) = a0;
        *(ushort2*)(ctxl + o0) = b0;
        *(ushort2*)(ctxh + o1) = a1;
        *(ushort2*)(ctxl + o1) = b1;
    }
}

// ---------------------------------------------------------------------------
// launch
// ---------------------------------------------------------------------------
extern "C" void kernel_launch(void* const* d_in, const int* in_sizes, int n_in,
                              void* d_out, int out_size)
{
    const float* x     = (const float*)d_in[0];
    const float* m     = (const float*)d_in[1];
    const float* gamma = (const float*)d_in[2];
    const float* beta  = (const float*)d_in[3];
    const float* Wqkv  = (const float*)d_in[4];
    const float* Wout  = (const float*)d_in[5];
    float* out = (float*)d_out;

    __nv_bfloat16 *xnh, *xnl, *wqh, *wql, *woh, *wol, *qkvh, *qkvl, *ctxh, *ctxl;
    cudaGetSymbolAddress((void**)&xnh,  g_xn_h);
    cudaGetSymbolAddress((void**)&xnl,  g_xn_l);
    cudaGetSymbolAddress((void**)&wqh,  g_wq_h);
    cudaGetSymbolAddress((void**)&wql,  g_wq_l);
    cudaGetSymbolAddress((void**)&woh,  g_wo_h);
    cudaGetSymbolAddress((void**)&wol,  g_wo_l);
    cudaGetSymbolAddress((void**)&qkvh, g_qkv_h);
    cudaGetSymbolAddress((void**)&qkvl, g_qkv_l);
    cudaGetSymbolAddress((void**)&ctxh, g_ctx_h);
    cudaGetSymbolAddress((void**)&ctxl, g_ctx_l);

    cudaFuncSetAttribute(mma_gemm,
                         cudaFuncAttributeMaxDynamicSharedMemorySize, GSMEM);
    cudaFuncSetAttribute(attn_mma_kernel,
                         cudaFuncAttributeMaxDynamicSharedMemorySize, ASMEM);

    // 1. LayerNorm (+ bf16 split)
    ln_kernel<<<NROWS, 256>>>(x, gamma, beta, xnh, xnl);

    // 2. weight transpose + split
    splitT_kernel<<<dim3(3*INNER/32, DMODEL/32), dim3(32,8)>>>(Wqkv, wqh, wql, DMODEL, 3*INNER);
    splitT_kernel<<<dim3(DMODEL/32,  INNER/32),  dim3(32,8)>>>(Wout, woh, wol, INNER, DMODEL);

    // 3. QKV projection -> bf16 hi/lo qkv
    mma_gemm<<<dim3(3*INNER/128, NROWS/128), 256, GSMEM>>>(
        xnh, xnl, wqh, wql, nullptr, qkvh, qkvl, 3*INNER);

    // 4. masked flash attention on tensor cores
    attn_mma_kernel<<<dim3(NSEQ/128, HEADS, BATCH), 256, ASMEM>>>(
        qkvh, qkvl, m, ctxh, ctxl);

    // 5. output projection -> fp32 out
    mma_gemm<<<dim3(DMODEL/128, NROWS/128), 256, GSMEM>>>(
        ctxh, ctxl, woh, wol, out, nullptr, nullptr, DMODEL);
}

// round 10
// speedup vs baseline: 2.9926x; 1.0807x over previous
#include <cuda_runtime.h>
#include <cuda_bf16.h>
#include <math.h>
#include <stdint.h>

// ---------------------------------------------------------------------------
// Problem constants
// ---------------------------------------------------------------------------
#define BATCH   2
#define NSEQ    2048
#define DMODEL  1024
#define HEADS   16
#define DH      64
#define INNER   1024
#define NROWS   (BATCH*NSEQ)   // 4096
#define SCALE   0.125f
#define SC2     (0.125f * 1.4426950408889634f)   // SCALE * log2(e)
#define LN_EPS  1e-5f

// ---------------------------------------------------------------------------
// Scratch (__device__ globals; no allocs allowed)
// ---------------------------------------------------------------------------
__device__ __nv_bfloat16 g_xn_h [(size_t)NROWS * DMODEL];
__device__ __nv_bfloat16 g_xn_l [(size_t)NROWS * DMODEL];
__device__ __nv_bfloat16 g_wq_h [(size_t)3*INNER * DMODEL];   // Wqkv^T [3072][1024]
__device__ __nv_bfloat16 g_wq_l [(size_t)3*INNER * DMODEL];
__device__ __nv_bfloat16 g_wo_h [(size_t)DMODEL * INNER];     // Wout^T
__device__ __nv_bfloat16 g_wo_l [(size_t)DMODEL * INNER];
__device__ __nv_bfloat16 g_qkv_h[(size_t)NROWS * 3 * INNER];  // bf16 hi QKV
__device__ __nv_bfloat16 g_qkv_l[(size_t)NROWS * 3 * INNER];  // bf16 lo QKV
__device__ __nv_bfloat16 g_ctx_h[(size_t)NROWS * INNER];
__device__ __nv_bfloat16 g_ctx_l[(size_t)NROWS * INNER];

// ---------------------------------------------------------------------------
// Helpers
// ---------------------------------------------------------------------------
__device__ __forceinline__ void split1(float v, __nv_bfloat16& h, __nv_bfloat16& l) {
    h = __float2bfloat16(v);
    l = __float2bfloat16(v - __bfloat162float(h));
}

__device__ __forceinline__ void ldsm4(uint32_t* r, uint32_t addr) {
    asm volatile("ldmatrix.sync.aligned.m8n8.x4.shared.b16 {%0,%1,%2,%3}, [%4];"
                 : "=r"(r[0]), "=r"(r[1]), "=r"(r[2]), "=r"(r[3]) : "r"(addr));
}

__device__ __forceinline__ void ldsm4t(uint32_t* r, uint32_t addr) {
    asm volatile("ldmatrix.sync.aligned.m8n8.x4.trans.shared.b16 {%0,%1,%2,%3}, [%4];"
                 : "=r"(r[0]), "=r"(r[1]), "=r"(r[2]), "=r"(r[3]) : "r"(addr));
}

__device__ __forceinline__ void mma16816(float* d, const uint32_t* a,
                                         const uint32_t* b) {
    asm volatile(
        "mma.sync.aligned.m16n8k16.row.col.f32.bf16.bf16.f32 "
        "{%0,%1,%2,%3}, {%4,%5,%6,%7}, {%8,%9}, {%0,%1,%2,%3};"
        : "+f"(d[0]), "+f"(d[1]), "+f"(d[2]), "+f"(d[3])
        : "r"(a[0]), "r"(a[1]), "r"(a[2]), "r"(a[3]), "r"(b[0]), "r"(b[1]));
}

__device__ __forceinline__ void cp16(uint32_t dst, const void* src) {
    asm volatile("cp.async.cg.shared.global [%0], [%1], 16;"
                 :: "r"(dst), "l"(__cvta_generic_to_global(src)));
}

__device__ __forceinline__ uint32_t packbf2(float a, float b) {
    __nv_bfloat162 t = __floats2bfloat162_rn(a, b);
    return *(uint32_t*)&t;
}

// ---------------------------------------------------------------------------
// Kernel 1: LayerNorm fused with bf16 hi/lo split output
// ---------------------------------------------------------------------------
__global__ __launch_bounds__(256) void ln_kernel(
    const float* __restrict__ x, const float* __restrict__ gamma,
    const float* __restrict__ beta,
    __nv_bfloat16* __restrict__ xh, __nv_bfloat16* __restrict__ xl)
{
    int row = blockIdx.x;
    int tid = threadIdx.x;
    const float4* xr = (const float4*)(x + (size_t)row * DMODEL);
    float4 v = xr[tid];

    float s  = v.x + v.y + v.z + v.w;
    float ss = v.x*v.x + v.y*v.y + v.z*v.z + v.w*v.w;
    #pragma unroll
    for (int off = 16; off; off >>= 1) {
        s  += __shfl_xor_sync(0xffffffffu, s,  off);
        ss += __shfl_xor_sync(0xffffffffu, ss, off);
    }
    __shared__ float sbuf[8], ssbuf[8];
    int warp = tid >> 5, lane = tid & 31;
    if (lane == 0) { sbuf[warp] = s; ssbuf[warp] = ss; }
    __syncthreads();
    s = 0.f; ss = 0.f;
    #pragma unroll
    for (int w = 0; w < 8; w++) { s += sbuf[w]; ss += ssbuf[w]; }

    float mu  = s * (1.0f / DMODEL);
    float var = ss * (1.0f / DMODEL) - mu * mu;
    float inv = rsqrtf(var + LN_EPS);

    float4 g  = ((const float4*)gamma)[tid];
    float4 be = ((const float4*)beta)[tid];
    float o0 = (v.x - mu) * inv * g.x + be.x;
    float o1 = (v.y - mu) * inv * g.y + be.y;
    float o2 = (v.z - mu) * inv * g.z + be.z;
    float o3 = (v.w - mu) * inv * g.w + be.w;

    __nv_bfloat16 h0,h1,h2,h3,l0,l1,l2,l3;
    split1(o0,h0,l0); split1(o1,h1,l1); split1(o2,h2,l2); split1(o3,h3,l3);
    size_t off = (size_t)row * DMODEL + tid * 4;
    ushort4 hv = { __bfloat16_as_ushort(h0), __bfloat16_as_ushort(h1),
                   __bfloat16_as_ushort(h2), __bfloat16_as_ushort(h3) };
    ushort4 lv = { __bfloat16_as_ushort(l0), __bfloat16_as_ushort(l1),
                   __bfloat16_as_ushort(l2), __bfloat16_as_ushort(l3) };
    *(ushort4*)(xh + off) = hv;
    *(ushort4*)(xl + off) = lv;
}

// ---------------------------------------------------------------------------
// Kernel 2: transpose + bf16 split for weights
// ---------------------------------------------------------------------------
__global__ __launch_bounds__(256) void splitT_kernel(
    const float* __restrict__ W,
    __nv_bfloat16* __restrict__ Th, __nv_bfloat16* __restrict__ Tl,
    int K, int N)
{
    __shared__ float t[32][33];
    int n0 = blockIdx.x * 32, k0 = blockIdx.y * 32;
    int tx = threadIdx.x, ty = threadIdx.y;
    #pragma unroll
    for (int j = 0; j < 4; j++) {
        int r = ty + j * 8;
        t[r][tx] = W[(size_t)(k0 + r) * N + n0 + tx];
    }
    __syncthreads();
    #pragma unroll
    for (int j = 0; j < 4; j++) {
        int r = ty + j * 8;
        float v = t[tx][r];
        __nv_bfloat16 h, l;
        split1(v, h, l);
        size_t o = (size_t)(n0 + r) * K + k0 + tx;
        Th[o] = h; Tl[o] = l;
    }
}

// ---------------------------------------------------------------------------
// Kernel 3: bf16x3-split GEMM on mma.sync.
// 3-stage cp.async pipeline, ONE __syncthreads per k-iteration, 2 CTAs/SM.
// Smem layout: 64-byte rows (32 bf16), XOR chunk swizzle c^=((row>>1)&3):
// 16B-aligned cp.async dsts, conflict-free ldmatrix phases.
// ---------------------------------------------------------------------------
#define GK    1024
#define GBK   32
#define GARR  (128 * 64)              // 8192 B per array (128 rows x 64 B)
#define GBLK  (4 * GARR)              // 32768 B per stage {Ah,Al,Bh,Bl}
#define GSMEM (3 * GBLK)              // 98304 B

__global__ __launch_bounds__(256, 2) void mma_gemm(
    const __nv_bfloat16* __restrict__ Ah, const __nv_bfloat16* __restrict__ Al,
    const __nv_bfloat16* __restrict__ Bh, const __nv_bfloat16* __restrict__ Bl,
    float* __restrict__ Cf,
    __nv_bfloat16* __restrict__ Ch, __nv_bfloat16* __restrict__ Cl,
    int N)
{
    extern __shared__ char smg[];
    const uint32_t sb = (uint32_t)__cvta_generic_to_shared(smg);

    const int tid  = threadIdx.x;
    const int lane = tid & 31, wid = tid >> 5;
    const int wm = wid >> 2, wn = wid & 3;
    const int m0 = blockIdx.y * 128, n0 = blockIdx.x * 128;

    // copy indices: chunk idx = tid and tid+256; r = idx>>2 (row), c = idx&3
    const int cr0 = (tid)       >> 2, cc0 = (tid)       & 3;
    const int cr1 = (tid + 256) >> 2, cc1 = (tid + 256) & 3;
    const uint32_t cd0 = (uint32_t)(cr0 * 64 + ((cc0 ^ ((cr0 >> 1) & 3)) << 4));
    const uint32_t cd1 = (uint32_t)(cr1 * 64 + ((cc1 ^ ((cr1 >> 1) & 3)) << 4));

    float acc[4][4][4];
    #pragma unroll
    for (int f = 0; f < 4; f++)
        #pragma unroll
        for (int j = 0; j < 4; j++)
            #pragma unroll
            for (int e = 0; e < 4; e++) acc[f][j][e] = 0.f;

    // ldmatrix per-lane constants (row-XOR folds to a lane constant:
    // f*16 and p*16 shift rows by multiples of 16 -> ((row>>1)&3) unchanged)
    const int arow = wm * 64 + (lane & 15);
    const uint32_t abase = (uint32_t)(arow * 64);
    const uint32_t axor  = (uint32_t)(((arow >> 1) & 3) << 4);
    const uint32_t achk  = (uint32_t)(lane >> 4);            // + ks*2

    const int brow = wn * 32 + (lane & 7) + ((lane >> 4) << 3);
    const uint32_t bbase = (uint32_t)(brow * 64);
    const uint32_t bxor  = (uint32_t)(((brow >> 1) & 3) << 4);
    const uint32_t bchk  = (uint32_t)((lane >> 3) & 1);      // + ks*2

#define STAGE_COPY(st, kc)                                                      \
    do {                                                                        \
        uint32_t so = sb + (uint32_t)(st) * GBLK;                               \
        size_t ga0 = (size_t)(m0 + cr0) * GK + (kc) + cc0 * 8;                  \
        size_t ga1 = (size_t)(m0 + cr1) * GK + (kc) + cc1 * 8;                  \
        size_t gb0 = (size_t)(n0 + cr0) * GK + (kc) + cc0 * 8;                  \
        size_t gb1 = (size_t)(n0 + cr1) * GK + (kc) + cc1 * 8;                  \
        cp16(so + cd0,            Ah + ga0); cp16(so + cd1,            Ah + ga1); \
        cp16(so + GARR + cd0,     Al + ga0); cp16(so + GARR + cd1,     Al + ga1); \
        cp16(so + 2*GARR + cd0,   Bh + gb0); cp16(so + 2*GARR + cd1,   Bh + gb1); \
        cp16(so + 3*GARR + cd0,   Bl + gb0); cp16(so + 3*GARR + cd1,   Bl + gb1); \
    } while (0)

    STAGE_COPY(0, 0);
    asm volatile("cp.async.commit_group;" ::: "memory");
    STAGE_COPY(1, GBK);
    asm volatile("cp.async.commit_group;" ::: "memory");

    const int nk = GK / GBK;   // 32
    for (int kt = 0; kt < nk; kt++) {
        const int st = kt % 3;
        asm volatile("cp.async.wait_group 1;" ::: "memory");
        __syncthreads();

        if (kt + 2 < nk) { STAGE_COPY((kt + 2) % 3, (kt + 2) * GBK); }
        asm volatile("cp.async.commit_group;" ::: "memory");

        const uint32_t so = sb + (uint32_t)st * GBLK;
        #pragma unroll
        for (int ks = 0; ks < 2; ks++) {
            uint32_t bh[2][4], bl[2][4];
            #pragma unroll
            for (int p = 0; p < 2; p++) {
                uint32_t o = so + 2*GARR + bbase + (uint32_t)(p * 16 * 64)
                           + ((((bchk + ks*2)) << 4) ^ bxor);
                ldsm4(bh[p], o);
                ldsm4(bl[p], o + GARR);
            }
            #pragma unroll
            for (int f = 0; f < 4; f++) {
                uint32_t ah[4], al[4];
                uint32_t o = so + abase + (uint32_t)(f * 16 * 64)
                           + ((((achk + ks*2)) << 4) ^ axor);
                ldsm4(ah, o);
                ldsm4(al, o + GARR);
                #pragma unroll
                for (int j = 0; j < 4; j++) {
                    const int p = j >> 1, sub = (j & 1) * 2;
                    uint32_t bhp[2] = { bh[p][sub], bh[p][sub + 1] };
                    uint32_t blp[2] = { bl[p][sub], bl[p][sub + 1] };
                    mma16816(acc[f][j], ah, bhp);
                    mma16816(acc[f][j], ah, blp);
                    mma16816(acc[f][j], al, bhp);
                }
            }
        }
    }

    const int erow = m0 + wm * 64 + (lane >> 2);
    const int ecol = n0 + wn * 32 + (lane & 3) * 2;
    if (Cf) {
        #pragma unroll
        for (int f = 0; f < 4; f++) {
            #pragma unroll
            for (int j = 0; j < 4; j++) {
                float* d0 = Cf + (size_t)(erow + f * 16)     * N + ecol + j * 8;
                float* d1 = Cf + (size_t)(erow + f * 16 + 8) * N + ecol + j * 8;
                *(float2*)d0 = make_float2(acc[f][j][0], acc[f][j][1]);
                *(float2*)d1 = make_float2(acc[f][j][2], acc[f][j][3]);
            }
        }
    } else {
        #pragma unroll
        for (int f = 0; f < 4; f++) {
            #pragma unroll
            for (int j = 0; j < 4; j++) {
                #pragma unroll
                for (int half = 0; half < 2; half++) {
                    size_t o = (size_t)(erow + f*16 + half*8) * N + ecol + j*8;
                    float v0 = acc[f][j][half*2], v1 = acc[f][j][half*2 + 1];
                    __nv_bfloat16 h0,l0,h1,l1;
                    split1(v0,h0,l0); split1(v1,h1,l1);
                    ushort2 hv = { __bfloat16_as_ushort(h0), __bfloat16_as_ushort(h1) };
                    ushort2 lv = { __bfloat16_as_ushort(l0), __bfloat16_as_ushort(l1) };
                    *(ushort2*)(Ch + o) = hv;
                    *(ushort2*)(Cl + o) = lv;
                }
            }
        }
    }
#undef STAGE_COPY
}

// ---------------------------------------------------------------------------
// Kernel 4: flash attention on mma.sync, bf16x3 split.
// 3-stage KV ring where stage 2 ALIASES the (dead after kt=0) Q region.
// ONE __syncthreads per k-iteration. Q fragments register-resident.
// (AST=72 elems -> 144-byte rows: 16B-aligned, conflict-free: 144r mod 128
//  spans all 8 slots.)
// ---------------------------------------------------------------------------
#define AST   72                       // smem row stride (bf16 elems)
#define AKB   (64 * AST * 2)           // 9216 B per K/V array
#define AKVST (4 * AKB)                // 36864 B per KV stage {Kh,Kl,Vh,Vl}
#define AQB   (128 * AST * 2)          // 18432 B per Q array
#define ASMEM (3 * AKVST)              // 110592 B; Q region == stage 2

__global__ __launch_bounds__(256, 2) void attn_mma_kernel(
    const __nv_bfloat16* __restrict__ qh_g, const __nv_bfloat16* __restrict__ ql_g,
    const float* __restrict__ mask,
    __nv_bfloat16* __restrict__ ctxh, __nv_bfloat16* __restrict__ ctxl)
{
    extern __shared__ char sma[];
    const uint32_t sb  = (uint32_t)__cvta_generic_to_shared(sma);
    const uint32_t uQh = sb + 2 * AKVST;      // aliases KV stage 2
    const uint32_t uQl = uQh + AQB;

    const int tid = threadIdx.x, lane = tid & 31, wq = tid >> 5;
    const int qt = blockIdx.x, h = blockIdx.y, b = blockIdx.z;
    const int q0 = qt * 128;
    const size_t rowbase = (size_t)b * NSEQ;
    const size_t qkstride = 3 * INNER;

#define KV_COPY(st, kc)                                                        \
    do {                                                                       \
        uint32_t so = sb + (uint32_t)(st) * AKVST;                             \
        _Pragma("unroll")                                                      \
        for (int t = 0; t < 2; t++) {                                          \
            int idx = tid + t * 256;                                           \
            int r = idx >> 3, c = idx & 7;                                     \
            uint32_t d = (uint32_t)(r * AST + c * 8) * 2;                      \
            size_t gk = (rowbase + (kc) + r) * qkstride + INNER   + h*DH + c*8;\
            size_t gv = (rowbase + (kc) + r) * qkstride + 2*INNER + h*DH + c*8;\
            cp16(so + d,         qh_g + gk);                                   \
            cp16(so + AKB + d,   ql_g + gk);                                   \
            cp16(so + 2*AKB + d, qh_g + gv);                                   \
            cp16(so + 3*AKB + d, ql_g + gv);                                   \
        }                                                                      \
    } while (0)

    // prologue: group0 = Q + KV stage0; group1 = KV stage1
    {
        #pragma unroll
        for (int t = 0; t < 4; t++) {
            int idx = tid + t * 256;
            int r = idx >> 3, c = idx & 7;
            uint32_t d = (uint32_t)(r * AST + c * 8) * 2;
            size_t g = (rowbase + q0 + r) * qkstride + h * DH + c * 8;
            cp16(uQh + d, qh_g + g);
            cp16(uQl + d, ql_g + g);
        }
    }
    KV_COPY(0, 0);
    asm volatile("cp.async.commit_group;" ::: "memory");
    KV_COPY(1, 64);
    asm volatile("cp.async.commit_group;" ::: "memory");

    uint32_t qfh[4][4], qfl[4][4];
    float oacc[8][4];
    #pragma unroll
    for (int j = 0; j < 8; j++)
        #pragma unroll
        for (int e = 0; e < 4; e++) oacc[j][e] = 0.f;
    float rmax0 = -1e30f, rmax1 = -1e30f, rsum0 = 0.f, rsum1 = 0.f;

    const uint32_t qoffb = (uint32_t)((wq*16 + (lane & 15)) * AST
                           + (lane >> 4) * 8) * 2;
    const uint32_t koffb = (uint32_t)(((lane & 7) + ((lane >> 4) << 3)) * AST
                           + ((lane >> 3) & 1) * 8) * 2;
    const uint32_t voffb = (uint32_t)(((lane & 15)) * AST + (lane >> 4) * 8) * 2;

    const int nk = NSEQ / 64;   // 32
    for (int kt = 0; kt < nk; kt++) {
        const int st = kt % 3;
        asm volatile("cp.async.wait_group 1;" ::: "memory");
        __syncthreads();

        if (kt == 0) {
            // extract Q fragments; then barrier before stage-2 copy overwrites Q
            #pragma unroll
            for (int kk = 0; kk < 4; kk++) {
                ldsm4(qfh[kk], uQh + qoffb + (uint32_t)(kk * 16) * 2);
                ldsm4(qfl[kk], uQl + qoffb + (uint32_t)(kk * 16) * 2);
            }
            __syncthreads();
        }

        if (kt + 2 < nk) { KV_COPY((kt + 2) % 3, (kt + 2) * 64); }
        asm volatile("cp.async.commit_group;" ::: "memory");

        const uint32_t so = sb + (uint32_t)st * AKVST;   // Kh base
        const uint32_t sV = so + 2 * AKB;

        // ---- S = Q K^T (3-term)
        float sacc[8][4];
        #pragma unroll
        for (int j = 0; j < 8; j++)
            #pragma unroll
            for (int e = 0; e < 4; e++) sacc[j][e] = 0.f;

        #pragma unroll
        for (int kk = 0; kk < 4; kk++) {
            #pragma unroll
            for (int jb = 0; jb < 4; jb++) {
                uint32_t kbh[4], kbl[4];
                uint32_t o = so + koffb + (uint32_t)(jb * 16 * AST + kk * 16) * 2;
                ldsm4(kbh, o);
                ldsm4(kbl, o + AKB);
                #pragma unroll
                for (int sub = 0; sub < 2; sub++) {
                    int j = jb * 2 + sub;
                    uint32_t bh[2] = { kbh[sub*2], kbh[sub*2+1] };
                    uint32_t bl[2] = { kbl[sub*2], kbl[sub*2+1] };
                    mma16816(sacc[j], qfh[kk], bh);
                    mma16816(sacc[j], qfh[kk], bl);
                    mma16816(sacc[j], qfl[kk], bh);
                }
            }
        }

        // ---- mask add (before scale), scale into exp2 domain
        {
            const int qrow = q0 + wq * 16 + (lane >> 2);
            const int kcol = kt * 64 + (lane & 3) * 2;
            const float* mg = mask + ((size_t)b * NSEQ + qrow) * NSEQ + kcol;
            #pragma unroll
            for (int j = 0; j < 8; j++) {
                float2 m0 = *(const float2*)(mg + j * 8);
                float2 m1 = *(const float2*)(mg + 8 * NSEQ + j * 8);
                sacc[j][0] = (sacc[j][0] + m0.x) * SC2;
                sacc[j][1] = (sacc[j][1] + m0.y) * SC2;
                sacc[j][2] = (sacc[j][2] + m1.x) * SC2;
                sacc[j][3] = (sacc[j][3] + m1.y) * SC2;
            }
        }

        // ---- online softmax (exp2 domain)
        float tm0 = -1e30f, tm1 = -1e30f;
        #pragma unroll
        for (int j = 0; j < 8; j++) {
            tm0 = fmaxf(tm0, fmaxf(sacc[j][0], sacc[j][1]));
            tm1 = fmaxf(tm1, fmaxf(sacc[j][2], sacc[j][3]));
        }
        #pragma unroll
        for (int off = 1; off <= 2; off <<= 1) {
            tm0 = fmaxf(tm0, __shfl_xor_sync(0xffffffffu, tm0, off));
            tm1 = fmaxf(tm1, __shfl_xor_sync(0xffffffffu, tm1, off));
        }
        float nm0 = fmaxf(rmax0, tm0), nm1 = fmaxf(rmax1, tm1);
        float corr0 = exp2f(rmax0 - nm0), corr1 = exp2f(rmax1 - nm1);
        rmax0 = nm0; rmax1 = nm1;

        float ps0 = 0.f, ps1 = 0.f;
        #pragma unroll
        for (int j = 0; j < 8; j++) {
            sacc[j][0] = exp2f(sacc[j][0] - nm0);
            sacc[j][1] = exp2f(sacc[j][1] - nm0);
            sacc[j][2] = exp2f(sacc[j][2] - nm1);
            sacc[j][3] = exp2f(sacc[j][3] - nm1);
            ps0 += sacc[j][0] + sacc[j][1];
            ps1 += sacc[j][2] + sacc[j][3];
        }
        #pragma unroll
        for (int off = 1; off <= 2; off <<= 1) {
            ps0 += __shfl_xor_sync(0xffffffffu, ps0, off);
            ps1 += __shfl_xor_sync(0xffffffffu, ps1, off);
        }
        rsum0 = rsum0 * corr0 + ps0;
        rsum1 = rsum1 * corr1 + ps1;

        #pragma unroll
        for (int j = 0; j < 8; j++) {
            oacc[j][0] *= corr0; oacc[j][1] *= corr0;
            oacc[j][2] *= corr1; oacc[j][3] *= corr1;
        }

        // ---- O += P V (3-term); pack P per-kp to bound register pressure
        #pragma unroll
        for (int kp = 0; kp < 4; kp++) {
            uint32_t pah[4], pal[4];
            {
                const int j0 = kp * 2, j1 = kp * 2 + 1;
                float p00 = sacc[j0][0], p01 = sacc[j0][1];
                float p02 = sacc[j0][2], p03 = sacc[j0][3];
                float p10 = sacc[j1][0], p11 = sacc[j1][1];
                float p12 = sacc[j1][2], p13 = sacc[j1][3];
                pah[0] = packbf2(p00, p01);
                pah[1] = packbf2(p02, p03);
                pah[2] = packbf2(p10, p11);
                pah[3] = packbf2(p12, p13);
                __nv_bfloat162* hp;
                hp = (__nv_bfloat162*)&pah[0];
                pal[0] = packbf2(p00 - __bfloat162float(hp->x), p01 - __bfloat162float(hp->y));
                hp = (__nv_bfloat162*)&pah[1];
                pal[1] = packbf2(p02 - __bfloat162float(hp->x), p03 - __bfloat162float(hp->y));
                hp = (__nv_bfloat162*)&pah[2];
                pal[2] = packbf2(p10 - __bfloat162float(hp->x), p11 - __bfloat162float(hp->y));
                hp = (__nv_bfloat162*)&pah[3];
                pal[3] = packbf2(p12 - __bfloat162float(hp->x), p13 - __bfloat162float(hp->y));
            }
            #pragma unroll
            for (int db = 0; db < 4; db++) {
                uint32_t vbh[4], vbl[4];
                uint32_t o = sV + voffb + (uint32_t)(kp * 16 * AST + db * 16) * 2;
                ldsm4t(vbh, o);
                ldsm4t(vbl, o + AKB);
                #pragma unroll
                for (int sub = 0; sub < 2; sub++) {
                    int j = db * 2 + sub;
                    uint32_t bh[2] = { vbh[sub*2], vbh[sub*2+1] };
                    uint32_t bl[2] = { vbl[sub*2], vbl[sub*2+1] };
                    mma16816(oacc[j], pah, bh);
                    mma16816(oacc[j], pah, bl);
                    mma16816(oacc[j], pal, bh);
                }
            }
        }
    }
#undef KV_COPY

    // ---- normalize + write ctx (bf16 hi/lo)
    const float inv0 = 1.0f / rsum0, inv1 = 1.0f / rsum1;
    const int row0 = q0 + wq * 16 + (lane >> 2);
    #pragma unroll
    for (int j = 0; j < 8; j++) {
        const int col = h * DH + j * 8 + (lane & 3) * 2;
        float v0 = oacc[j][0] * inv0, v1 = oacc[j][1] * inv0;
        float v2 = oacc[j][2] * inv1, v3 = oacc[j][3] * inv1;
        __nv_bfloat16 h0,l0,h1,l1,h2,l2,h3,l3;
        split1(v0,h0,l0); split1(v1,h1,l1); split1(v2,h2,l2); split1(v3,h3,l3);
        size_t o0 = (rowbase + row0)     * (size_t)INNER + col;
        size_t o1 = (rowbase + row0 + 8) * (size_t)INNER + col;
        ushort2 a0 = { __bfloat16_as_ushort(h0), __bfloat16_as_ushort(h1) };
        ushort2 b0 = { __bfloat16_as_ushort(l0), __bfloat16_as_ushort(l1) };
        ushort2 a1 = { __bfloat16_as_ushort(h2), __bfloat16_as_ushort(h3) };
        ushort2 b1 = { __bfloat16_as_ushort(l2), __bfloat16_as_ushort(l3) };
        *(ushort2*)(ctxh + o0) = a0;
        *(ushort2*)(ctxl + o0) = b0;
        *(ushort2*)(ctxh + o1) = a1;
        *(ushort2*)(ctxl + o1) = b1;
    }
}

// ---------------------------------------------------------------------------
// launch
// ---------------------------------------------------------------------------
extern "C" void kernel_launch(void* const* d_in, const int* in_sizes, int n_in,
                              void* d_out, int out_size)
{
    const float* x     = (const float*)d_in[0];
    const float* m     = (const float*)d_in[1];
    const float* gamma = (const float*)d_in[2];
    const float* beta  = (const float*)d_in[3];
    const float* Wqkv  = (const float*)d_in[4];
    const float* Wout  = (const float*)d_in[5];
    float* out = (float*)d_out;

    __nv_bfloat16 *xnh, *xnl, *wqh, *wql, *woh, *wol, *qkvh, *qkvl, *ctxh, *ctxl;
    cudaGetSymbolAddress((void**)&xnh,  g_xn_h);
    cudaGetSymbolAddress((void**)&xnl,  g_xn_l);
    cudaGetSymbolAddress((void**)&wqh,  g_wq_h);
    cudaGetSymbolAddress((void**)&wql,  g_wq_l);
    cudaGetSymbolAddress((void**)&woh,  g_wo_h);
    cudaGetSymbolAddress((void**)&wol,  g_wo_l);
    cudaGetSymbolAddress((void**)&qkvh, g_qkv_h);
    cudaGetSymbolAddress((void**)&qkvl, g_qkv_l);
    cudaGetSymbolAddress((void**)&ctxh, g_ctx_h);
    cudaGetSymbolAddress((void**)&ctxl, g_ctx_l);

    cudaFuncSetAttribute(mma_gemm,
                         cudaFuncAttributeMaxDynamicSharedMemorySize, GSMEM);
    cudaFuncSetAttribute(attn_mma_kernel,
                         cudaFuncAttributeMaxDynamicSharedMemorySize, ASMEM);

    // 1. LayerNorm (+ bf16 split)
    ln_kernel<<<NROWS, 256>>>(x, gamma, beta, xnh, xnl);

    // 2. weight transpose + split
    splitT_kernel<<<dim3(3*INNER/32, DMODEL/32), dim3(32,8)>>>(Wqkv, wqh, wql, DMODEL, 3*INNER);
    splitT_kernel<<<dim3(DMODEL/32,  INNER/32),  dim3(32,8)>>>(Wout, woh, wol, INNER, DMODEL);

    // 3. QKV projection -> bf16 hi/lo qkv
    mma_gemm<<<dim3(3*INNER/128, NROWS/128), 256, GSMEM>>>(
        xnh, xnl, wqh, wql, nullptr, qkvh, qkvl, 3*INNER);

    // 4. masked flash attention on tensor cores
    attn_mma_kernel<<<dim3(NSEQ/128, HEADS, BATCH), 256, ASMEM>>>(
        qkvh, qkvl, m, ctxh, ctxl);

    // 5. output projection -> fp32 out
    mma_gemm<<<dim3(DMODEL/128, NROWS/128), 256, GSMEM>>>(
        ctxh, ctxl, woh, wol, out, nullptr, nullptr, DMODEL);
}